// round 1
// baseline (speedup 1.0000x reference)
#include <cuda_runtime.h>

#define D_MODEL 2048
#define SEQ     2048
#define BATCH   2
#define NHEADS  16
#define HDIM    128
#define M_TOK   (BATCH*SEQ)   // 4096

// ---- persistent scratch (allocation-free rule: __device__ globals) ----
__device__ float g_q[M_TOK * D_MODEL];
__device__ float g_k[M_TOK * D_MODEL];
__device__ float g_v[M_TOK * D_MODEL];
__device__ float g_ctx[M_TOK * D_MODEL];

// ============================================================
// SGEMM (NT): C[m,n] = (sum_k A[m,k]*B[n,k] + bias[n]) * alpha
// A:[M,K] row-major, B:[N,K] row-major (torch Linear weight)
// ============================================================
#define GBM 128
#define GBN 128
#define GBK 16

__global__ __launch_bounds__(256) void sgemm_nt(
    const float* __restrict__ A, const float* __restrict__ B,
    const float* __restrict__ bias, float* __restrict__ C,
    int M, int N, int K, float alpha)
{
    __shared__ float As[GBK][GBM + 4];
    __shared__ float Bs[GBK][GBN + 4];
    const int tid = threadIdx.x;
    const int tx = tid & 15;     // 0..15 -> n
    const int ty = tid >> 4;     // 0..15 -> m
    const int bm = blockIdx.y * GBM;
    const int bn = blockIdx.x * GBN;

    float acc[8][8];
#pragma unroll
    for (int i = 0; i < 8; i++)
#pragma unroll
        for (int j = 0; j < 8; j++) acc[i][j] = 0.f;

    for (int k0 = 0; k0 < K; k0 += GBK) {
#pragma unroll
        for (int it = 0; it < 2; ++it) {
            int slot = tid + it * 256;          // 0..511
            int row  = slot >> 2;               // 0..127
            int c4   = (slot & 3) << 2;         // 0,4,8,12
            float4 a = *(const float4*)(A + (size_t)(bm + row) * K + k0 + c4);
            As[c4 + 0][row] = a.x; As[c4 + 1][row] = a.y;
            As[c4 + 2][row] = a.z; As[c4 + 3][row] = a.w;
            float4 b = *(const float4*)(B + (size_t)(bn + row) * K + k0 + c4);
            Bs[c4 + 0][row] = b.x; Bs[c4 + 1][row] = b.y;
            Bs[c4 + 2][row] = b.z; Bs[c4 + 3][row] = b.w;
        }
        __syncthreads();
#pragma unroll
        for (int kk = 0; kk < GBK; ++kk) {
            float ra[8], rb[8];
            *(float4*)&ra[0] = *(const float4*)&As[kk][ty * 8];
            *(float4*)&ra[4] = *(const float4*)&As[kk][ty * 8 + 4];
            *(float4*)&rb[0] = *(const float4*)&Bs[kk][tx * 8];
            *(float4*)&rb[4] = *(const float4*)&Bs[kk][tx * 8 + 4];
#pragma unroll
            for (int i = 0; i < 8; i++)
#pragma unroll
                for (int j = 0; j < 8; j++)
                    acc[i][j] += ra[i] * rb[j];
        }
        __syncthreads();
    }

#pragma unroll
    for (int i = 0; i < 8; i++) {
        int m = bm + ty * 8 + i;
#pragma unroll
        for (int j = 0; j < 8; j += 4) {
            int n = bn + tx * 8 + j;
            float4 o;
            o.x = (acc[i][j + 0] + bias[n + 0]) * alpha;
            o.y = (acc[i][j + 1] + bias[n + 1]) * alpha;
            o.z = (acc[i][j + 2] + bias[n + 2]) * alpha;
            o.w = (acc[i][j + 3] + bias[n + 3]) * alpha;
            *(float4*)(C + (size_t)m * N + n) = o;
        }
    }
}

// ============================================================
// Flash attention (fp32, online softmax)
// grid: (SEQ/128, BATCH*NHEADS), 512 threads
// ============================================================
#define ABQ 128
#define ABK 64

#define OFF_Q    0
#define SZ_Q     (128 * 132)
#define OFF_KT   (OFF_Q + SZ_Q)
#define SZ_KT    (128 * 68)
#define OFF_V    (OFF_KT + SZ_KT)
#define SZ_V     (64 * 132)
#define OFF_S    (OFF_V + SZ_V)
#define SZ_S     (128 * 68)
#define OFF_MADD (OFF_S + SZ_S)
#define OFF_M    (OFF_MADD + 64)
#define OFF_L    (OFF_M + 128)
#define OFF_C    (OFF_L + 128)
#define SMEM_FLOATS (OFF_C + 128)   // 43200 floats = 172.8 KB

__global__ __launch_bounds__(512) void attn_kernel(const float* __restrict__ mask)
{
    extern __shared__ float sm[];
    float* Qs   = sm + OFF_Q;    // [128][132]
    float* KT   = sm + OFF_KT;   // [128 k][68] holds K^T
    float* Vs   = sm + OFF_V;    // [64][132]
    float* Ss   = sm + OFF_S;    // [128][68]
    float* madd = sm + OFF_MADD; // [64]
    float* mrow = sm + OFF_M;    // [128]
    float* lrow = sm + OFF_L;    // [128]
    float* crow = sm + OFF_C;    // [128]

    const int tid = threadIdx.x;
    const int b   = blockIdx.y >> 4;
    const int h   = blockIdx.y & 15;
    const int q0  = blockIdx.x * ABQ;
    const size_t base = (size_t)b * SEQ * D_MODEL + h * HDIM;

    // load Q tile [128 x 128]
#pragma unroll
    for (int it = 0; it < 8; ++it) {
        int slot = tid + it * 512;        // 0..4095
        int row  = slot >> 5;             // 0..127
        int c    = (slot & 31) << 2;      // 0..124
        float4 v = *(const float4*)(g_q + base + (size_t)(q0 + row) * D_MODEL + c);
        *(float4*)&Qs[row * 132 + c] = v;
    }
    if (tid < 128) { mrow[tid] = -1e30f; lrow[tid] = 0.f; }

    float o0[16], o1[16];
#pragma unroll
    for (int i = 0; i < 16; i++) { o0[i] = 0.f; o1[i] = 0.f; }

    const int ty = tid >> 3;   // 0..63: rows {ty, ty+64}
    const int tx = tid & 7;    // 0..7
    const int rr = tid >> 2;   // 0..127 softmax row
    const int rq = tid & 3;    // 0..3 quarter

    for (int kv0 = 0; kv0 < SEQ; kv0 += ABK) {
        __syncthreads();  // smem reuse guard (also orders Q load / init on iter 0)
        // load K^T and V tiles (64 kv rows x 128 dims)
#pragma unroll
        for (int it = 0; it < 4; ++it) {
            int slot = tid + it * 512;    // 0..2047
            int row  = slot >> 5;         // 0..63
            int c    = (slot & 31) << 2;
            size_t g = base + (size_t)(kv0 + row) * D_MODEL + c;
            float4 kv = *(const float4*)(g_k + g);
            KT[(c + 0) * 68 + row] = kv.x;
            KT[(c + 1) * 68 + row] = kv.y;
            KT[(c + 2) * 68 + row] = kv.z;
            KT[(c + 3) * 68 + row] = kv.w;
            float4 vv = *(const float4*)(g_v + g);
            *(float4*)&Vs[row * 132 + c] = vv;
        }
        if (tid < 64) {
            float mv = mask[b * SEQ + kv0 + tid];
            madd[tid] = (1.0f - mv) * -1e30f;
        }
        __syncthreads();

        // S = Q @ K^T   (rows {ty,ty+64}, cols tx*8..+7)
        float s0[8], s1[8];
#pragma unroll
        for (int j = 0; j < 8; j++) { s0[j] = 0.f; s1[j] = 0.f; }
#pragma unroll 4
        for (int k = 0; k < HDIM; ++k) {
            float qa = Qs[ty * 132 + k];
            float qb = Qs[(ty + 64) * 132 + k];
            float kr[8];
            *(float4*)&kr[0] = *(const float4*)&KT[k * 68 + tx * 8];
            *(float4*)&kr[4] = *(const float4*)&KT[k * 68 + tx * 8 + 4];
#pragma unroll
            for (int j = 0; j < 8; j++) { s0[j] += qa * kr[j]; s1[j] += qb * kr[j]; }
        }
#pragma unroll
        for (int j = 0; j < 8; j++) {
            Ss[ty * 68 + tx * 8 + j]        = s0[j];
            Ss[(ty + 64) * 68 + tx * 8 + j] = s1[j];
        }
        __syncthreads();

        // online softmax (4 threads per row, 16 cols each)
        float sv[16];
        float mloc = -1e30f;
#pragma unroll
        for (int i = 0; i < 16; i++) {
            sv[i] = Ss[rr * 68 + rq * 16 + i] + madd[rq * 16 + i];
            mloc = fmaxf(mloc, sv[i]);
        }
        mloc = fmaxf(mloc, __shfl_xor_sync(0xffffffffu, mloc, 1));
        mloc = fmaxf(mloc, __shfl_xor_sync(0xffffffffu, mloc, 2));
        float mold = mrow[rr];
        float mnew = fmaxf(mold, mloc);
        float psum = 0.f;
#pragma unroll
        for (int i = 0; i < 16; i++) {
            float e = __expf(sv[i] - mnew);
            Ss[rr * 68 + rq * 16 + i] = e;
            psum += e;
        }
        psum += __shfl_xor_sync(0xffffffffu, psum, 1);
        psum += __shfl_xor_sync(0xffffffffu, psum, 2);
        if (rq == 0) {
            float corr = __expf(mold - mnew);
            crow[rr] = corr;
            lrow[rr] = lrow[rr] * corr + psum;
            mrow[rr] = mnew;
        }
        __syncthreads();

        // O = O*corr + P @ V   (rows {ty,ty+64}, cols tx*16..+15)
        float c0 = crow[ty], c1 = crow[ty + 64];
#pragma unroll
        for (int i = 0; i < 16; i++) { o0[i] *= c0; o1[i] *= c1; }
#pragma unroll 2
        for (int j = 0; j < ABK; ++j) {
            float p0 = Ss[ty * 68 + j];
            float p1 = Ss[(ty + 64) * 68 + j];
            float vr[16];
            *(float4*)&vr[0]  = *(const float4*)&Vs[j * 132 + tx * 16];
            *(float4*)&vr[4]  = *(const float4*)&Vs[j * 132 + tx * 16 + 4];
            *(float4*)&vr[8]  = *(const float4*)&Vs[j * 132 + tx * 16 + 8];
            *(float4*)&vr[12] = *(const float4*)&Vs[j * 132 + tx * 16 + 12];
#pragma unroll
            for (int i = 0; i < 16; i++) { o0[i] += p0 * vr[i]; o1[i] += p1 * vr[i]; }
        }
    }
    __syncthreads();

    float inv0 = 1.0f / lrow[ty];
    float inv1 = 1.0f / lrow[ty + 64];
#pragma unroll
    for (int i = 0; i < 16; i += 4) {
        float4 a, c;
        a.x = o0[i] * inv0; a.y = o0[i + 1] * inv0;
        a.z = o0[i + 2] * inv0; a.w = o0[i + 3] * inv0;
        *(float4*)(g_ctx + base + (size_t)(q0 + ty) * D_MODEL + tx * 16 + i) = a;
        c.x = o1[i] * inv1; c.y = o1[i + 1] * inv1;
        c.z = o1[i + 2] * inv1; c.w = o1[i + 3] * inv1;
        *(float4*)(g_ctx + base + (size_t)(q0 + ty + 64) * D_MODEL + tx * 16 + i) = c;
    }
}

// ============================================================
extern "C" void kernel_launch(void* const* d_in, const int* in_sizes, int n_in,
                              void* d_out, int out_size)
{
    const float* x    = (const float*)d_in[0];
    const float* mask = (const float*)d_in[1];
    const float* Wq   = (const float*)d_in[2];
    const float* bq   = (const float*)d_in[3];
    const float* Wk   = (const float*)d_in[4];
    const float* bk   = (const float*)d_in[5];
    const float* Wv   = (const float*)d_in[6];
    const float* bv   = (const float*)d_in[7];
    const float* Wo   = (const float*)d_in[8];
    const float* bo   = (const float*)d_in[9];
    float* out = (float*)d_out;

    float *q, *k, *v, *ctx;
    cudaGetSymbolAddress((void**)&q,   g_q);
    cudaGetSymbolAddress((void**)&k,   g_k);
    cudaGetSymbolAddress((void**)&v,   g_v);
    cudaGetSymbolAddress((void**)&ctx, g_ctx);

    dim3 ggrid(D_MODEL / GBN, M_TOK / GBM);
    const float scale = 0.08838834764831845f;  // 1/sqrt(128)

    sgemm_nt<<<ggrid, 256>>>(x, Wq, bq, q, M_TOK, D_MODEL, D_MODEL, scale);
    sgemm_nt<<<ggrid, 256>>>(x, Wk, bk, k, M_TOK, D_MODEL, D_MODEL, 1.0f);
    sgemm_nt<<<ggrid, 256>>>(x, Wv, bv, v, M_TOK, D_MODEL, D_MODEL, 1.0f);

    cudaFuncSetAttribute(attn_kernel, cudaFuncAttributeMaxDynamicSharedMemorySize,
                         SMEM_FLOATS * 4);
    attn_kernel<<<dim3(SEQ / ABQ, BATCH * NHEADS), 512, SMEM_FLOATS * 4>>>(mask);

    sgemm_nt<<<ggrid, 256>>>(ctx, Wo, bo, out, M_TOK, D_MODEL, D_MODEL, 1.0f);
}

// round 3
// speedup vs baseline: 1.2216x; 1.2216x over previous
#include <cuda_runtime.h>
#include <cuda_bf16.h>
#include <cstdint>

#define D_MODEL 2048
#define SEQ     2048
#define BATCH   2
#define NHEADS  16
#define HDIM    128
#define M_TOK   (BATCH*SEQ)   // 4096

// tcgen05 is arch-specific: only available in the code=sm_103a pass.
// The harness also runs a compute_103 (virtual) PTX pass which must not see
// tcgen05 instructions; gate on the arch-specific feature macros.
#if defined(__CUDA_ARCH_FEAT_SM103_ALL) || defined(__CUDA_ARCH_FEAT_SM100_ALL) || \
    (defined(__CUDA_ARCH_SPECIFIC__) && (__CUDA_ARCH_SPECIFIC__ >= 1000))
#define HAS_TCGEN05 1
#else
#define HAS_TCGEN05 0
#endif

// ---- persistent scratch (allocation-free rule: __device__ globals) ----
__device__ float g_q[M_TOK * D_MODEL];
__device__ float g_k[M_TOK * D_MODEL];
__device__ float g_v[M_TOK * D_MODEL];
__device__ float g_ctx[M_TOK * D_MODEL];

__device__ __nv_bfloat16 g_xh[M_TOK * D_MODEL];
__device__ __nv_bfloat16 g_xl[M_TOK * D_MODEL];
__device__ __nv_bfloat16 g_chh[M_TOK * D_MODEL];
__device__ __nv_bfloat16 g_cll[M_TOK * D_MODEL];
__device__ __nv_bfloat16 g_wh[4][D_MODEL * D_MODEL];
__device__ __nv_bfloat16 g_wl[4][D_MODEL * D_MODEL];

// ============================================================
// PTX helpers (sm_103a tcgen05 / mbarrier)
// ============================================================
__device__ __forceinline__ uint32_t smem_u32(const void* p) {
    uint32_t a;
    asm("{ .reg .u64 t; cvta.to.shared.u64 t, %1; cvt.u32.u64 %0, t; }" : "=r"(a) : "l"(p));
    return a;
}
__device__ __forceinline__ uint32_t elect_one_pred() {
    uint32_t p;
    asm volatile("{ .reg .pred p; elect.sync _|p, 0xFFFFFFFF; selp.b32 %0, 1, 0, p; }" : "=r"(p));
    return p;
}
static constexpr uint64_t SMEM_DESC_BASE_SW128 =
    (uint64_t(2) << 61) | (uint64_t(1) << 46) | (uint64_t(64) << 32) | (uint64_t(1) << 16);
#define MAKE_SMEM_DESC(base_addr) \
    (SMEM_DESC_BASE_SW128 | ((uint64_t)((base_addr) >> 4) & 0x3FFF))
#define SMEM_SWIZZLE_128B(off) ((off) ^ (((off) >> 3) & 0x70))

#define MBARRIER_INIT(mbar, count) \
    asm volatile("mbarrier.init.shared.b64 [%0], %1;" \
                 :: "r"((uint32_t)(mbar)), "r"((uint32_t)(count)) : "memory")
#define MBARRIER_INVAL(mbar) \
    asm volatile("mbarrier.inval.shared.b64 [%0];" :: "r"((uint32_t)(mbar)) : "memory")
#define MBARRIER_WAIT_PARITY(mbar, parity) do {                                          \
    uint32_t _m = (uint32_t)(mbar);                                                      \
    uint32_t _p = (uint32_t)(parity);                                                    \
    uint32_t _done;                                                                      \
    asm volatile("{ .reg .pred p; mbarrier.try_wait.parity.acquire.cta.shared::cta.b64 " \
                 "p, [%1], %2; selp.b32 %0, 1, 0, p; }"                                  \
                 : "=r"(_done) : "r"(_m), "r"(_p) : "memory");                           \
    if (!_done) {                                                                        \
        asm volatile("{ .reg .pred P1; WL_%=: "                                          \
                     "mbarrier.try_wait.parity.acquire.cta.shared::cta.b64 P1, [%0], %1, 0x989680; " \
                     "@P1 bra.uni WD_%=; bra.uni WL_%=; WD_%=: }"                        \
                     :: "r"(_m), "r"(_p) : "memory");                                    \
    }                                                                                    \
} while (0)
#define FENCE_PROXY_ASYNC_SHARED_CTA() \
    asm volatile("fence.proxy.async.shared::cta;" ::: "memory")

#if HAS_TCGEN05
#define TCGEN05_ALLOC(smem_addr, nCols) \
    asm volatile("tcgen05.alloc.cta_group::1.sync.aligned.shared::cta.b32 [%0], %1;" \
                 :: "r"((uint32_t)(smem_addr)), "r"((uint32_t)(nCols)) : "memory")
#define TCGEN05_DEALLOC(tmem_addr, nCols) \
    asm volatile("tcgen05.dealloc.cta_group::1.sync.aligned.b32 %0, %1;" \
                 :: "r"(tmem_addr), "r"((uint32_t)(nCols)))
#define TCGEN05_RELINQUISH() \
    asm volatile("tcgen05.relinquish_alloc_permit.cta_group::1.sync.aligned;")
#define TCGEN05_COMMIT(mbar) \
    asm volatile("tcgen05.commit.cta_group::1.mbarrier::arrive::one.shared::cluster.b64 [%0];" \
                 :: "r"((uint32_t)(mbar)) : "memory")
#define TCGEN05_FENCE_AFTER() \
    asm volatile("tcgen05.fence::after_thread_sync;" ::: "memory")
#define TCGEN05_FENCE_BEFORE() \
    asm volatile("tcgen05.fence::before_thread_sync;" ::: "memory")
#define TCGEN05_WAIT_LD() \
    asm volatile("tcgen05.wait::ld.sync.aligned;" ::: "memory")

#define TCGEN05_LD_32X32B_X32(r, tmem_addr) \
    asm volatile( \
        "tcgen05.ld.sync.aligned.32x32b.x32.b32 " \
        "{%0, %1, %2, %3, %4, %5, %6, %7, " \
        " %8, %9, %10, %11, %12, %13, %14, %15, " \
        " %16, %17, %18, %19, %20, %21, %22, %23, " \
        " %24, %25, %26, %27, %28, %29, %30, %31}, [%32];" \
        : "=r"((r)[0]),  "=r"((r)[1]),  "=r"((r)[2]),  "=r"((r)[3]), \
          "=r"((r)[4]),  "=r"((r)[5]),  "=r"((r)[6]),  "=r"((r)[7]), \
          "=r"((r)[8]),  "=r"((r)[9]),  "=r"((r)[10]), "=r"((r)[11]), \
          "=r"((r)[12]), "=r"((r)[13]), "=r"((r)[14]), "=r"((r)[15]), \
          "=r"((r)[16]), "=r"((r)[17]), "=r"((r)[18]), "=r"((r)[19]), \
          "=r"((r)[20]), "=r"((r)[21]), "=r"((r)[22]), "=r"((r)[23]), \
          "=r"((r)[24]), "=r"((r)[25]), "=r"((r)[26]), "=r"((r)[27]), \
          "=r"((r)[28]), "=r"((r)[29]), "=r"((r)[30]), "=r"((r)[31]) \
        : "r"(tmem_addr))

// SS-mode bf16 MMA, cta_group::1
__device__ __forceinline__ void mma_f16_ss(uint32_t d_tmem, uint64_t a_desc, uint64_t b_desc,
                                           uint32_t idesc, uint32_t enable) {
    asm volatile(
        "{\n\t"
        ".reg .pred p;\n\t"
        "setp.ne.u32 p, %4, 0;\n\t"
        "tcgen05.mma.cta_group::1.kind::f16 [%0], %1, %2, %3, {%5, %5, %5, %5}, p;\n\t"
        "}"
        :: "r"(d_tmem), "l"(a_desc), "l"(b_desc), "r"(idesc), "r"(enable), "r"(0u)
        : "memory");
}
#endif  // HAS_TCGEN05

// ============================================================
// fp32 -> (bf16 hi, bf16 lo) split
// ============================================================
__global__ __launch_bounds__(256) void split_kernel(
    const float* __restrict__ src, __nv_bfloat16* __restrict__ hi,
    __nv_bfloat16* __restrict__ lo, int n4)
{
    int i = blockIdx.x * blockDim.x + threadIdx.x;
    if (i >= n4) return;
    float4 v = ((const float4*)src)[i];
    __nv_bfloat16 h0 = __float2bfloat16(v.x);
    __nv_bfloat16 h1 = __float2bfloat16(v.y);
    __nv_bfloat16 h2 = __float2bfloat16(v.z);
    __nv_bfloat16 h3 = __float2bfloat16(v.w);
    __nv_bfloat16 l0 = __float2bfloat16(v.x - __bfloat162float(h0));
    __nv_bfloat16 l1 = __float2bfloat16(v.y - __bfloat162float(h1));
    __nv_bfloat16 l2 = __float2bfloat16(v.z - __bfloat162float(h2));
    __nv_bfloat16 l3 = __float2bfloat16(v.w - __bfloat162float(h3));
    __nv_bfloat162* ph = (__nv_bfloat162*)hi;
    __nv_bfloat162* pl = (__nv_bfloat162*)lo;
    ph[2 * i]     = __nv_bfloat162(h0, h1);
    ph[2 * i + 1] = __nv_bfloat162(h2, h3);
    pl[2 * i]     = __nv_bfloat162(l0, l1);
    pl[2 * i + 1] = __nv_bfloat162(l2, l3);
}

// ============================================================
// tcgen05 GEMM (NT): C[m,n] = (sum_k A[m,k]*B[n,k] + bias[n]) * alpha
// A,B pre-split into bf16 hi/lo. 128x128 tile, K-chunk = 64 (bf16),
// 3 MMAs per k-step (hi*hi + lo*hi + hi*lo), fp32 accum in TMEM.
// ============================================================
#define KCH 64                         // bf16 k per chunk
#define NCH (D_MODEL / KCH)            // 32
#define TILE_B 16384                   // 128 rows x 128 bytes
#define STAGE_B (4 * TILE_B)           // A_hi A_lo B_hi B_lo
#define SM_TILES 1024                  // tile area offset (tmem ptr + mbar below)
#define GEMM_SMEM (SM_TILES + 2 * STAGE_B)   // 132096 bytes

// idesc: kind::f16, dtype F32, a/b BF16 K-major, M=128, N=128
#define GEMM_IDESC 0x8200490u

__global__ __launch_bounds__(256) void gemm_tc(
    const __nv_bfloat16* __restrict__ Ah, const __nv_bfloat16* __restrict__ Al,
    const __nv_bfloat16* __restrict__ Bh, const __nv_bfloat16* __restrict__ Bl,
    const float* __restrict__ bias, float* __restrict__ C, float alpha)
{
#if HAS_TCGEN05
    extern __shared__ char sm[];
    const uint32_t smb = smem_u32(sm);
    const int tid = threadIdx.x;
    const int wid = tid >> 5;
    const int lid = tid & 31;
    const int bm = blockIdx.y * 128;
    const int bn = blockIdx.x * 128;
    const int K = D_MODEL;

    if (wid == 0) TCGEN05_ALLOC(smb + 0, 128);
    if (tid == 0) MBARRIER_INIT(smb + 8, 1);

    const __nv_bfloat16* tp0 = Ah + (size_t)bm * K;
    const __nv_bfloat16* tp1 = Al + (size_t)bm * K;
    const __nv_bfloat16* tp2 = Bh + (size_t)bn * K;
    const __nv_bfloat16* tp3 = Bl + (size_t)bn * K;

    // chunk loader: 4 tiles of 128 rows x 64 bf16 (128B/row, SW128 swizzled)
#define LOAD_CHUNK(stage, c)                                                     \
    do {                                                                         \
        int k0 = (c) * KCH;                                                      \
        char* sb = sm + SM_TILES + (stage) * STAGE_B;                            \
        _Pragma("unroll")                                                        \
        for (int t = 0; t < 16; ++t) {                                           \
            const __nv_bfloat16* p = (t < 4) ? tp0 : (t < 8) ? tp1               \
                                   : (t < 12) ? tp2 : tp3;                       \
            int w = tid + (t & 3) * 256;   /* 0..1023 */                         \
            int row = w >> 3;                                                    \
            int cc = w & 7;                                                      \
            uint4 v = *(const uint4*)(p + (size_t)row * K + k0 + cc * 8);        \
            int so = (t >> 2) * TILE_B + SMEM_SWIZZLE_128B(row * 128 + cc * 16); \
            *(uint4*)(sb + so) = v;                                              \
        }                                                                        \
    } while (0)

    LOAD_CHUNK(0, 0);
    FENCE_PROXY_ASYNC_SHARED_CTA();
    __syncthreads();

    uint32_t tmem;
    asm volatile("ld.shared.b32 %0, [%1];" : "=r"(tmem) : "r"(smb + 0));

    for (int c = 0; c < NCH; ++c) {
        int cur = c & 1;
        if (wid == 0 && elect_one_pred()) {
            uint32_t sa = smb + SM_TILES + cur * STAGE_B;
            uint64_t dAh = MAKE_SMEM_DESC(sa);
            uint64_t dAl = MAKE_SMEM_DESC(sa + TILE_B);
            uint64_t dBh = MAKE_SMEM_DESC(sa + 2 * TILE_B);
            uint64_t dBl = MAKE_SMEM_DESC(sa + 3 * TILE_B);
#pragma unroll
            for (int ks = 0; ks < 4; ++ks) {
                mma_f16_ss(tmem, dAh + ks * 2, dBh + ks * 2, GEMM_IDESC, (c | ks) != 0);
                mma_f16_ss(tmem, dAl + ks * 2, dBh + ks * 2, GEMM_IDESC, 1);
                mma_f16_ss(tmem, dAh + ks * 2, dBl + ks * 2, GEMM_IDESC, 1);
            }
            TCGEN05_COMMIT(smb + 8);
        }
        if (c + 1 < NCH) {
            LOAD_CHUNK(cur ^ 1, c + 1);
            FENCE_PROXY_ASYNC_SHARED_CTA();
        }
        MBARRIER_WAIT_PARITY(smb + 8, c & 1);
        __syncthreads();
    }

    // epilogue: warps 0-3 cols 0..63, warps 4-7 cols 64..127; sub = wid&3 rows
    TCGEN05_FENCE_AFTER();
    const int wg = wid >> 2;
    const int sub = wid & 3;
    const int n0 = bn + wg * 64;
    uint32_t r[64];
    TCGEN05_LD_32X32B_X32(r, tmem + wg * 64);
    TCGEN05_LD_32X32B_X32(r + 32, tmem + wg * 64 + 32);
    TCGEN05_WAIT_LD();
    TCGEN05_FENCE_BEFORE();

    const int m = bm + sub * 32 + lid;
    float* crow = C + (size_t)m * D_MODEL + n0;
#pragma unroll
    for (int j = 0; j < 64; j += 4) {
        float4 o;
        o.x = (__uint_as_float(r[j + 0]) + bias[n0 + j + 0]) * alpha;
        o.y = (__uint_as_float(r[j + 1]) + bias[n0 + j + 1]) * alpha;
        o.z = (__uint_as_float(r[j + 2]) + bias[n0 + j + 2]) * alpha;
        o.w = (__uint_as_float(r[j + 3]) + bias[n0 + j + 3]) * alpha;
        *(float4*)(crow + j) = o;
    }

    __syncthreads();
    if (tid == 0) MBARRIER_INVAL(smb + 8);
    __syncthreads();
    if (wid == 0) {
        TCGEN05_RELINQUISH();
        TCGEN05_DEALLOC(tmem, 128);
    }
#undef LOAD_CHUNK
#endif  // HAS_TCGEN05
}

// ============================================================
// Flash attention (fp32, online softmax) — unchanged from R1
// ============================================================
#define ABQ 128
#define ABK 64

#define OFF_Q    0
#define SZ_Q     (128 * 132)
#define OFF_KT   (OFF_Q + SZ_Q)
#define SZ_KT    (128 * 68)
#define OFF_V    (OFF_KT + SZ_KT)
#define SZ_V     (64 * 132)
#define OFF_S    (OFF_V + SZ_V)
#define SZ_S     (128 * 68)
#define OFF_MADD (OFF_S + SZ_S)
#define OFF_M    (OFF_MADD + 64)
#define OFF_L    (OFF_M + 128)
#define OFF_C    (OFF_L + 128)
#define SMEM_FLOATS (OFF_C + 128)   // 43200 floats = 172.8 KB

__global__ __launch_bounds__(512) void attn_kernel(const float* __restrict__ mask)
{
    extern __shared__ float smf[];
    float* Qs   = smf + OFF_Q;
    float* KT   = smf + OFF_KT;
    float* Vs   = smf + OFF_V;
    float* Ss   = smf + OFF_S;
    float* madd = smf + OFF_MADD;
    float* mrow = smf + OFF_M;
    float* lrow = smf + OFF_L;
    float* crow = smf + OFF_C;

    const int tid = threadIdx.x;
    const int b   = blockIdx.y >> 4;
    const int h   = blockIdx.y & 15;
    const int q0  = blockIdx.x * ABQ;
    const size_t base = (size_t)b * SEQ * D_MODEL + h * HDIM;

#pragma unroll
    for (int it = 0; it < 8; ++it) {
        int slot = tid + it * 512;
        int row  = slot >> 5;
        int c    = (slot & 31) << 2;
        float4 v = *(const float4*)(g_q + base + (size_t)(q0 + row) * D_MODEL + c);
        *(float4*)&Qs[row * 132 + c] = v;
    }
    if (tid < 128) { mrow[tid] = -1e30f; lrow[tid] = 0.f; }

    float o0[16], o1[16];
#pragma unroll
    for (int i = 0; i < 16; i++) { o0[i] = 0.f; o1[i] = 0.f; }

    const int ty = tid >> 3;
    const int tx = tid & 7;
    const int rr = tid >> 2;
    const int rq = tid & 3;

    for (int kv0 = 0; kv0 < SEQ; kv0 += ABK) {
        __syncthreads();
#pragma unroll
        for (int it = 0; it < 4; ++it) {
            int slot = tid + it * 512;
            int row  = slot >> 5;
            int c    = (slot & 31) << 2;
            size_t g = base + (size_t)(kv0 + row) * D_MODEL + c;
            float4 kv = *(const float4*)(g_k + g);
            KT[(c + 0) * 68 + row] = kv.x;
            KT[(c + 1) * 68 + row] = kv.y;
            KT[(c + 2) * 68 + row] = kv.z;
            KT[(c + 3) * 68 + row] = kv.w;
            float4 vv = *(const float4*)(g_v + g);
            *(float4*)&Vs[row * 132 + c] = vv;
        }
        if (tid < 64) {
            float mv = mask[b * SEQ + kv0 + tid];
            madd[tid] = (1.0f - mv) * -1e30f;
        }
        __syncthreads();

        float s0[8], s1[8];
#pragma unroll
        for (int j = 0; j < 8; j++) { s0[j] = 0.f; s1[j] = 0.f; }
#pragma unroll 4
        for (int k = 0; k < HDIM; ++k) {
            float qa = Qs[ty * 132 + k];
            float qb = Qs[(ty + 64) * 132 + k];
            float kr[8];
            *(float4*)&kr[0] = *(const float4*)&KT[k * 68 + tx * 8];
            *(float4*)&kr[4] = *(const float4*)&KT[k * 68 + tx * 8 + 4];
#pragma unroll
            for (int j = 0; j < 8; j++) { s0[j] += qa * kr[j]; s1[j] += qb * kr[j]; }
        }
#pragma unroll
        for (int j = 0; j < 8; j++) {
            Ss[ty * 68 + tx * 8 + j]        = s0[j];
            Ss[(ty + 64) * 68 + tx * 8 + j] = s1[j];
        }
        __syncthreads();

        float sv[16];
        float mloc = -1e30f;
#pragma unroll
        for (int i = 0; i < 16; i++) {
            sv[i] = Ss[rr * 68 + rq * 16 + i] + madd[rq * 16 + i];
            mloc = fmaxf(mloc, sv[i]);
        }
        mloc = fmaxf(mloc, __shfl_xor_sync(0xffffffffu, mloc, 1));
        mloc = fmaxf(mloc, __shfl_xor_sync(0xffffffffu, mloc, 2));
        float mold = mrow[rr];
        float mnew = fmaxf(mold, mloc);
        float psum = 0.f;
#pragma unroll
        for (int i = 0; i < 16; i++) {
            float e = __expf(sv[i] - mnew);
            Ss[rr * 68 + rq * 16 + i] = e;
            psum += e;
        }
        psum += __shfl_xor_sync(0xffffffffu, psum, 1);
        psum += __shfl_xor_sync(0xffffffffu, psum, 2);
        if (rq == 0) {
            float corr = __expf(mold - mnew);
            crow[rr] = corr;
            lrow[rr] = lrow[rr] * corr + psum;
            mrow[rr] = mnew;
        }
        __syncthreads();

        float c0 = crow[ty], c1 = crow[ty + 64];
#pragma unroll
        for (int i = 0; i < 16; i++) { o0[i] *= c0; o1[i] *= c1; }
#pragma unroll 2
        for (int j = 0; j < ABK; ++j) {
            float p0 = Ss[ty * 68 + j];
            float p1 = Ss[(ty + 64) * 68 + j];
            float vr[16];
            *(float4*)&vr[0]  = *(const float4*)&Vs[j * 132 + tx * 16];
            *(float4*)&vr[4]  = *(const float4*)&Vs[j * 132 + tx * 16 + 4];
            *(float4*)&vr[8]  = *(const float4*)&Vs[j * 132 + tx * 16 + 8];
            *(float4*)&vr[12] = *(const float4*)&Vs[j * 132 + tx * 16 + 12];
#pragma unroll
            for (int i = 0; i < 16; i++) { o0[i] += p0 * vr[i]; o1[i] += p1 * vr[i]; }
        }
    }
    __syncthreads();

    float inv0 = 1.0f / lrow[ty];
    float inv1 = 1.0f / lrow[ty + 64];
#pragma unroll
    for (int i = 0; i < 16; i += 4) {
        float4 a, c;
        a.x = o0[i] * inv0; a.y = o0[i + 1] * inv0;
        a.z = o0[i + 2] * inv0; a.w = o0[i + 3] * inv0;
        *(float4*)(g_ctx + base + (size_t)(q0 + ty) * D_MODEL + tx * 16 + i) = a;
        c.x = o1[i] * inv1; c.y = o1[i + 1] * inv1;
        c.z = o1[i + 2] * inv1; c.w = o1[i + 3] * inv1;
        *(float4*)(g_ctx + base + (size_t)(q0 + ty + 64) * D_MODEL + tx * 16 + i) = c;
    }
}

// ============================================================
extern "C" void kernel_launch(void* const* d_in, const int* in_sizes, int n_in,
                              void* d_out, int out_size)
{
    const float* x    = (const float*)d_in[0];
    const float* mask = (const float*)d_in[1];
    const float* Wq   = (const float*)d_in[2];
    const float* bq   = (const float*)d_in[3];
    const float* Wk   = (const float*)d_in[4];
    const float* bk   = (const float*)d_in[5];
    const float* Wv   = (const float*)d_in[6];
    const float* bv   = (const float*)d_in[7];
    const float* Wo   = (const float*)d_in[8];
    const float* bo   = (const float*)d_in[9];
    float* out = (float*)d_out;

    float *q, *k, *v, *ctx;
    cudaGetSymbolAddress((void**)&q,   g_q);
    cudaGetSymbolAddress((void**)&k,   g_k);
    cudaGetSymbolAddress((void**)&v,   g_v);
    cudaGetSymbolAddress((void**)&ctx, g_ctx);
    __nv_bfloat16 *xh, *xl, *ch, *cl, *wh, *wl;
    cudaGetSymbolAddress((void**)&xh, g_xh);
    cudaGetSymbolAddress((void**)&xl, g_xl);
    cudaGetSymbolAddress((void**)&ch, g_chh);
    cudaGetSymbolAddress((void**)&cl, g_cll);
    cudaGetSymbolAddress((void**)&wh, g_wh);
    cudaGetSymbolAddress((void**)&wl, g_wl);

    const int WN = D_MODEL * D_MODEL;          // 4.2M
    const int XN = M_TOK * D_MODEL;            // 8.4M
    const float scale = 0.08838834764831845f;  // 1/sqrt(128)

    // splits
    split_kernel<<<XN / 4 / 256, 256>>>(x, xh, xl, XN / 4);
    split_kernel<<<WN / 4 / 256, 256>>>(Wq, wh + 0ll * WN, wl + 0ll * WN, WN / 4);
    split_kernel<<<WN / 4 / 256, 256>>>(Wk, wh + 1ll * WN, wl + 1ll * WN, WN / 4);
    split_kernel<<<WN / 4 / 256, 256>>>(Wv, wh + 2ll * WN, wl + 2ll * WN, WN / 4);
    split_kernel<<<WN / 4 / 256, 256>>>(Wo, wh + 3ll * WN, wl + 3ll * WN, WN / 4);

    cudaFuncSetAttribute(gemm_tc, cudaFuncAttributeMaxDynamicSharedMemorySize, GEMM_SMEM);
    dim3 ggrid(D_MODEL / 128, M_TOK / 128);
    gemm_tc<<<ggrid, 256, GEMM_SMEM>>>(xh, xl, wh + 0ll * WN, wl + 0ll * WN, bq, q, scale);
    gemm_tc<<<ggrid, 256, GEMM_SMEM>>>(xh, xl, wh + 1ll * WN, wl + 1ll * WN, bk, k, 1.0f);
    gemm_tc<<<ggrid, 256, GEMM_SMEM>>>(xh, xl, wh + 2ll * WN, wl + 2ll * WN, bv, v, 1.0f);

    cudaFuncSetAttribute(attn_kernel, cudaFuncAttributeMaxDynamicSharedMemorySize,
                         SMEM_FLOATS * 4);
    attn_kernel<<<dim3(SEQ / ABQ, BATCH * NHEADS), 512, SMEM_FLOATS * 4>>>(mask);

    split_kernel<<<XN / 4 / 256, 256>>>(ctx, ch, cl, XN / 4);
    gemm_tc<<<ggrid, 256, GEMM_SMEM>>>(ch, cl, wh + 3ll * WN, wl + 3ll * WN, bo, out, 1.0f);
}

// round 4
// speedup vs baseline: 1.3977x; 1.1441x over previous
#include <cuda_runtime.h>
#include <cuda_bf16.h>
#include <cstdint>

#define D_MODEL 2048
#define SEQ     2048
#define BATCH   2
#define NHEADS  16
#define HDIM    128
#define M_TOK   (BATCH*SEQ)   // 4096

// tcgen05 is arch-specific: only available in the code=sm_103a pass.
#if defined(__CUDA_ARCH_FEAT_SM103_ALL) || defined(__CUDA_ARCH_FEAT_SM100_ALL) || \
    (defined(__CUDA_ARCH_SPECIFIC__) && (__CUDA_ARCH_SPECIFIC__ >= 1000))
#define HAS_TCGEN05 1
#else
#define HAS_TCGEN05 0
#endif

// ---- persistent scratch ----
__device__ float g_q[M_TOK * D_MODEL];
__device__ float g_k[M_TOK * D_MODEL];
__device__ float g_v[M_TOK * D_MODEL];
__device__ float g_ctx[M_TOK * D_MODEL];

// packed (tile-contiguous, pre-swizzled) bf16 hi/lo operands
__device__ __nv_bfloat16 g_xh[M_TOK * D_MODEL];
__device__ __nv_bfloat16 g_xl[M_TOK * D_MODEL];
__device__ __nv_bfloat16 g_chh[M_TOK * D_MODEL];
__device__ __nv_bfloat16 g_cll[M_TOK * D_MODEL];
__device__ __nv_bfloat16 g_wh[4][D_MODEL * D_MODEL];
__device__ __nv_bfloat16 g_wl[4][D_MODEL * D_MODEL];

// ============================================================
// PTX helpers
// ============================================================
__device__ __forceinline__ uint32_t smem_u32(const void* p) {
    uint32_t a;
    asm("{ .reg .u64 t; cvta.to.shared.u64 t, %1; cvt.u32.u64 %0, t; }" : "=r"(a) : "l"(p));
    return a;
}
__device__ __forceinline__ uint32_t elect_one_pred() {
    uint32_t p;
    asm volatile("{ .reg .pred p; elect.sync _|p, 0xFFFFFFFF; selp.b32 %0, 1, 0, p; }" : "=r"(p));
    return p;
}
static constexpr uint64_t SMEM_DESC_BASE_SW128 =
    (uint64_t(2) << 61) | (uint64_t(1) << 46) | (uint64_t(64) << 32) | (uint64_t(1) << 16);
#define MAKE_SMEM_DESC(base_addr) \
    (SMEM_DESC_BASE_SW128 | ((uint64_t)((base_addr) >> 4) & 0x3FFF))
#define SMEM_SWIZZLE_128B(off) ((off) ^ (((off) >> 3) & 0x70))

#define MBARRIER_INIT(mbar, count) \
    asm volatile("mbarrier.init.shared.b64 [%0], %1;" \
                 :: "r"((uint32_t)(mbar)), "r"((uint32_t)(count)) : "memory")
#define MBARRIER_INVAL(mbar) \
    asm volatile("mbarrier.inval.shared.b64 [%0];" :: "r"((uint32_t)(mbar)) : "memory")
#define MBARRIER_EXPECT_TX(mbar, bytes) \
    asm volatile("mbarrier.arrive.expect_tx.shared.b64 _, [%0], %1;" \
                 :: "r"((uint32_t)(mbar)), "r"((uint32_t)(bytes)) : "memory")
#define MBARRIER_WAIT_PARITY(mbar, parity) do {                                          \
    uint32_t _m = (uint32_t)(mbar);                                                      \
    uint32_t _p = (uint32_t)(parity);                                                    \
    uint32_t _done;                                                                      \
    asm volatile("{ .reg .pred p; mbarrier.try_wait.parity.acquire.cta.shared::cta.b64 " \
                 "p, [%1], %2; selp.b32 %0, 1, 0, p; }"                                  \
                 : "=r"(_done) : "r"(_m), "r"(_p) : "memory");                           \
    if (!_done) {                                                                        \
        asm volatile("{ .reg .pred P1; WL_%=: "                                          \
                     "mbarrier.try_wait.parity.acquire.cta.shared::cta.b64 P1, [%0], %1, 0x989680; " \
                     "@P1 bra.uni WD_%=; bra.uni WL_%=; WD_%=: }"                        \
                     :: "r"(_m), "r"(_p) : "memory");                                    \
    }                                                                                    \
} while (0)

// bulk async copy gmem -> smem with transaction-count completion
#define BULK_CP(dst_smem, src_gmem, bytes, mbar) \
    asm volatile("cp.async.bulk.shared::cluster.global.mbarrier::complete_tx::bytes " \
                 "[%0], [%1], %2, [%3];" \
                 :: "r"((uint32_t)(dst_smem)), "l"(src_gmem), "r"((uint32_t)(bytes)), \
                    "r"((uint32_t)(mbar)) : "memory")

#if HAS_TCGEN05
#define TCGEN05_ALLOC(smem_addr, nCols) \
    asm volatile("tcgen05.alloc.cta_group::1.sync.aligned.shared::cta.b32 [%0], %1;" \
                 :: "r"((uint32_t)(smem_addr)), "r"((uint32_t)(nCols)) : "memory")
#define TCGEN05_DEALLOC(tmem_addr, nCols) \
    asm volatile("tcgen05.dealloc.cta_group::1.sync.aligned.b32 %0, %1;" \
                 :: "r"(tmem_addr), "r"((uint32_t)(nCols)))
#define TCGEN05_RELINQUISH() \
    asm volatile("tcgen05.relinquish_alloc_permit.cta_group::1.sync.aligned;")
#define TCGEN05_COMMIT(mbar) \
    asm volatile("tcgen05.commit.cta_group::1.mbarrier::arrive::one.shared::cluster.b64 [%0];" \
                 :: "r"((uint32_t)(mbar)) : "memory")
#define TCGEN05_FENCE_AFTER() \
    asm volatile("tcgen05.fence::after_thread_sync;" ::: "memory")
#define TCGEN05_FENCE_BEFORE() \
    asm volatile("tcgen05.fence::before_thread_sync;" ::: "memory")
#define TCGEN05_WAIT_LD() \
    asm volatile("tcgen05.wait::ld.sync.aligned;" ::: "memory")

#define TCGEN05_LD_32X32B_X32(r, tmem_addr) \
    asm volatile( \
        "tcgen05.ld.sync.aligned.32x32b.x32.b32 " \
        "{%0, %1, %2, %3, %4, %5, %6, %7, " \
        " %8, %9, %10, %11, %12, %13, %14, %15, " \
        " %16, %17, %18, %19, %20, %21, %22, %23, " \
        " %24, %25, %26, %27, %28, %29, %30, %31}, [%32];" \
        : "=r"((r)[0]),  "=r"((r)[1]),  "=r"((r)[2]),  "=r"((r)[3]), \
          "=r"((r)[4]),  "=r"((r)[5]),  "=r"((r)[6]),  "=r"((r)[7]), \
          "=r"((r)[8]),  "=r"((r)[9]),  "=r"((r)[10]), "=r"((r)[11]), \
          "=r"((r)[12]), "=r"((r)[13]), "=r"((r)[14]), "=r"((r)[15]), \
          "=r"((r)[16]), "=r"((r)[17]), "=r"((r)[18]), "=r"((r)[19]), \
          "=r"((r)[20]), "=r"((r)[21]), "=r"((r)[22]), "=r"((r)[23]), \
          "=r"((r)[24]), "=r"((r)[25]), "=r"((r)[26]), "=r"((r)[27]), \
          "=r"((r)[28]), "=r"((r)[29]), "=r"((r)[30]), "=r"((r)[31]) \
        : "r"(tmem_addr))

__device__ __forceinline__ void mma_f16_ss(uint32_t d_tmem, uint64_t a_desc, uint64_t b_desc,
                                           uint32_t idesc, uint32_t enable) {
    asm volatile(
        "{\n\t"
        ".reg .pred p;\n\t"
        "setp.ne.u32 p, %4, 0;\n\t"
        "tcgen05.mma.cta_group::1.kind::f16 [%0], %1, %2, %3, {%5, %5, %5, %5}, p;\n\t"
        "}"
        :: "r"(d_tmem), "l"(a_desc), "l"(b_desc), "r"(idesc), "r"(enable), "r"(0u)
        : "memory");
}
#endif  // HAS_TCGEN05

// ============================================================
// fp32 -> (bf16 hi, bf16 lo) split + tile packing.
// Output layout: tiles of 128 rows x 64 cols bf16 (16KB), SW128-swizzled
// internally, ordered chunk-major: tile(c, rt) at ((c * nrt + rt) * 16KB).
// src is [rows, 2048] fp32, rows = nrt*128.
// ============================================================
__global__ __launch_bounds__(256) void split_pack(
    const float* __restrict__ src, __nv_bfloat16* __restrict__ hi,
    __nv_bfloat16* __restrict__ lo, int nrt, int n8)
{
    int i = blockIdx.x * blockDim.x + threadIdx.x;
    if (i >= n8) return;
    int elem = i * 8;
    int row = elem >> 11;          // / 2048
    int col = elem & 2047;
    int rt = row >> 7, r = row & 127;
    int c  = col >> 6, kc = col & 63;
    size_t tb = ((size_t)(c * nrt + rt)) << 14;           // tile byte base
    uint32_t so = SMEM_SWIZZLE_128B((uint32_t)(r * 128 + kc * 2));

    float4 v0 = ((const float4*)src)[i * 2];
    float4 v1 = ((const float4*)src)[i * 2 + 1];
    float f[8] = {v0.x, v0.y, v0.z, v0.w, v1.x, v1.y, v1.z, v1.w};
    __nv_bfloat16 h[8], l[8];
#pragma unroll
    for (int j = 0; j < 8; j++) {
        h[j] = __float2bfloat16(f[j]);
        l[j] = __float2bfloat16(f[j] - __bfloat162float(h[j]));
    }
    *(uint4*)((char*)hi + tb + so) = *(uint4*)h;
    *(uint4*)((char*)lo + tb + so) = *(uint4*)l;
}

// ============================================================
// tcgen05 GEMM (NT): C[m,n] = (sum_k A[m,k]*B[n,k] + bias[n]) * alpha
// Tile 128(M) x 256(N), K-chunk = 64 bf16, 3 MMAs per k-step (hi*hi,
// lo*hi, hi*lo), fp32 accum in TMEM. Operands pre-packed + pre-swizzled;
// loads via cp.async.bulk, 2-stage pipeline, single control thread.
// ============================================================
#define KCH  64
#define NCH  (D_MODEL / KCH)    // 32
#define NRT_A 32                // 4096/128 row tiles (activations)
#define NRT_W 16                // 2048/128 row tiles (weights)
#define TIL  16384              // tile bytes
#define STG  (6 * TIL)          // stage: Ah,Al (16K each) + Bh,Bl (32K each) = 96KB
#define SMB0 1024
#define GEMM_SMEM (SMB0 + 2 * STG)   // 197632 B

// idesc: kind::f16, F32 accum, BF16 a/b K-major, M=128, N=256
#define GEMM_IDESC 0x8400490u

__global__ __launch_bounds__(256) void gemm_tc(
    const __nv_bfloat16* __restrict__ Ah, const __nv_bfloat16* __restrict__ Al,
    const __nv_bfloat16* __restrict__ Bh, const __nv_bfloat16* __restrict__ Bl,
    const float* __restrict__ bias, float* __restrict__ C, float alpha)
{
#if HAS_TCGEN05
    extern __shared__ char sm[];
    const uint32_t smb = smem_u32(sm);
    const int tid = threadIdx.x;
    const int wid = tid >> 5;
    const int lid = tid & 31;
    const int rm = blockIdx.y;            // A row-tile (128 rows)
    const int bx = blockIdx.x;            // B 256-col block

    if (wid == 0) TCGEN05_ALLOC(smb + 0, 256);
    if (tid == 0) {
#pragma unroll
        for (int s = 0; s < 2; ++s) {
            MBARRIER_INIT(smb + 64 + 16 * s, 1);   // full[s]
            MBARRIER_INIT(smb + 96 + 16 * s, 1);   // empty[s]
        }
    }
    __syncthreads();

    uint32_t tmem;
    asm volatile("ld.shared.b32 %0, [%1];" : "=r"(tmem) : "r"(smb + 0));

    if (wid == 0 && elect_one_pred()) {
        const char* pAh = (const char*)Ah;
        const char* pAl = (const char*)Al;
        const char* pBh = (const char*)Bh;
        const char* pBl = (const char*)Bl;

#define LOAD_CHUNK(c, s)                                                        \
        do {                                                                    \
            uint32_t st = smb + SMB0 + (s) * STG;                               \
            uint32_t fb = smb + 64 + 16 * (s);                                  \
            size_t ao = ((size_t)((c) * NRT_A + rm)) << 14;                     \
            size_t bo = ((size_t)((c) * NRT_W + 2 * bx)) << 14;                 \
            MBARRIER_EXPECT_TX(fb, 6 * TIL);                                    \
            BULK_CP(st,           pAh + ao, TIL,     fb);                       \
            BULK_CP(st + TIL,     pAl + ao, TIL,     fb);                       \
            BULK_CP(st + 2 * TIL, pBh + bo, 2 * TIL, fb);                       \
            BULK_CP(st + 4 * TIL, pBl + bo, 2 * TIL, fb);                       \
        } while (0)

        LOAD_CHUNK(0, 0);
        LOAD_CHUNK(1, 1);

        for (int c = 0; c < NCH; ++c) {
            int s = c & 1, ph = (c >> 1) & 1;
            uint32_t st = smb + SMB0 + s * STG;
            MBARRIER_WAIT_PARITY(smb + 64 + 16 * s, ph);
            uint64_t dAh = MAKE_SMEM_DESC(st);
            uint64_t dAl = MAKE_SMEM_DESC(st + TIL);
            uint64_t dBh = MAKE_SMEM_DESC(st + 2 * TIL);
            uint64_t dBl = MAKE_SMEM_DESC(st + 4 * TIL);
#pragma unroll
            for (int ks = 0; ks < 4; ++ks) {
                mma_f16_ss(tmem, dAh + ks * 2, dBh + ks * 2, GEMM_IDESC, (c | ks) != 0);
                mma_f16_ss(tmem, dAl + ks * 2, dBh + ks * 2, GEMM_IDESC, 1);
                mma_f16_ss(tmem, dAh + ks * 2, dBl + ks * 2, GEMM_IDESC, 1);
            }
            TCGEN05_COMMIT(smb + 96 + 16 * s);
            if (c + 2 < NCH) {
                MBARRIER_WAIT_PARITY(smb + 96 + 16 * s, ph);
                LOAD_CHUNK(c + 2, s);
            }
        }
        // wait for final chunk's MMAs (in-order completion covers all)
        MBARRIER_WAIT_PARITY(smb + 96 + 16 * ((NCH - 1) & 1), ((NCH - 1) >> 1) & 1);
#undef LOAD_CHUNK
    }
    __syncthreads();
    TCGEN05_FENCE_AFTER();

    // epilogue: 8 warps; wg = col half (0/1), sub = row group
    const int wg = wid >> 2;
    const int sub = wid & 3;
    const int m = blockIdx.y * 128 + sub * 32 + lid;
    float* crow = C + (size_t)m * D_MODEL;
#pragma unroll
    for (int cb = 0; cb < 4; ++cb) {
        uint32_t r[32];
        TCGEN05_LD_32X32B_X32(r, tmem + wg * 128 + cb * 32);
        TCGEN05_WAIT_LD();
        int n0 = bx * 256 + wg * 128 + cb * 32;
#pragma unroll
        for (int j = 0; j < 32; j += 4) {
            float4 o;
            o.x = (__uint_as_float(r[j + 0]) + bias[n0 + j + 0]) * alpha;
            o.y = (__uint_as_float(r[j + 1]) + bias[n0 + j + 1]) * alpha;
            o.z = (__uint_as_float(r[j + 2]) + bias[n0 + j + 2]) * alpha;
            o.w = (__uint_as_float(r[j + 3]) + bias[n0 + j + 3]) * alpha;
            *(float4*)(crow + n0 + j) = o;
        }
    }
    TCGEN05_FENCE_BEFORE();

    __syncthreads();
    if (tid == 0) {
#pragma unroll
        for (int s = 0; s < 2; ++s) {
            MBARRIER_INVAL(smb + 64 + 16 * s);
            MBARRIER_INVAL(smb + 96 + 16 * s);
        }
    }
    __syncthreads();
    if (wid == 0) {
        TCGEN05_RELINQUISH();
        TCGEN05_DEALLOC(tmem, 256);
    }
#endif  // HAS_TCGEN05
}

// ============================================================
// Flash attention (fp32, online softmax) — unchanged (passing R3 version)
// ============================================================
#define ABQ 128
#define ABK 64

#define OFF_Q    0
#define SZ_Q     (128 * 132)
#define OFF_KT   (OFF_Q + SZ_Q)
#define SZ_KT    (128 * 68)
#define OFF_V    (OFF_KT + SZ_KT)
#define SZ_V     (64 * 132)
#define OFF_S    (OFF_V + SZ_V)
#define SZ_S     (128 * 68)
#define OFF_MADD (OFF_S + SZ_S)
#define OFF_M    (OFF_MADD + 64)
#define OFF_L    (OFF_M + 128)
#define OFF_C    (OFF_L + 128)
#define SMEM_FLOATS (OFF_C + 128)

__global__ __launch_bounds__(512) void attn_kernel(const float* __restrict__ mask)
{
    extern __shared__ float smf[];
    float* Qs   = smf + OFF_Q;
    float* KT   = smf + OFF_KT;
    float* Vs   = smf + OFF_V;
    float* Ss   = smf + OFF_S;
    float* madd = smf + OFF_MADD;
    float* mrow = smf + OFF_M;
    float* lrow = smf + OFF_L;
    float* crow = smf + OFF_C;

    const int tid = threadIdx.x;
    const int b   = blockIdx.y >> 4;
    const int h   = blockIdx.y & 15;
    const int q0  = blockIdx.x * ABQ;
    const size_t base = (size_t)b * SEQ * D_MODEL + h * HDIM;

#pragma unroll
    for (int it = 0; it < 8; ++it) {
        int slot = tid + it * 512;
        int row  = slot >> 5;
        int c    = (slot & 31) << 2;
        float4 v = *(const float4*)(g_q + base + (size_t)(q0 + row) * D_MODEL + c);
        *(float4*)&Qs[row * 132 + c] = v;
    }
    if (tid < 128) { mrow[tid] = -1e30f; lrow[tid] = 0.f; }

    float o0[16], o1[16];
#pragma unroll
    for (int i = 0; i < 16; i++) { o0[i] = 0.f; o1[i] = 0.f; }

    const int ty = tid >> 3;
    const int tx = tid & 7;
    const int rr = tid >> 2;
    const int rq = tid & 3;

    for (int kv0 = 0; kv0 < SEQ; kv0 += ABK) {
        __syncthreads();
#pragma unroll
        for (int it = 0; it < 4; ++it) {
            int slot = tid + it * 512;
            int row  = slot >> 5;
            int c    = (slot & 31) << 2;
            size_t g = base + (size_t)(kv0 + row) * D_MODEL + c;
            float4 kv = *(const float4*)(g_k + g);
            KT[(c + 0) * 68 + row] = kv.x;
            KT[(c + 1) * 68 + row] = kv.y;
            KT[(c + 2) * 68 + row] = kv.z;
            KT[(c + 3) * 68 + row] = kv.w;
            float4 vv = *(const float4*)(g_v + g);
            *(float4*)&Vs[row * 132 + c] = vv;
        }
        if (tid < 64) {
            float mv = mask[b * SEQ + kv0 + tid];
            madd[tid] = (1.0f - mv) * -1e30f;
        }
        __syncthreads();

        float s0[8], s1[8];
#pragma unroll
        for (int j = 0; j < 8; j++) { s0[j] = 0.f; s1[j] = 0.f; }
#pragma unroll 4
        for (int k = 0; k < HDIM; ++k) {
            float qa = Qs[ty * 132 + k];
            float qb = Qs[(ty + 64) * 132 + k];
            float kr[8];
            *(float4*)&kr[0] = *(const float4*)&KT[k * 68 + tx * 8];
            *(float4*)&kr[4] = *(const float4*)&KT[k * 68 + tx * 8 + 4];
#pragma unroll
            for (int j = 0; j < 8; j++) { s0[j] += qa * kr[j]; s1[j] += qb * kr[j]; }
        }
#pragma unroll
        for (int j = 0; j < 8; j++) {
            Ss[ty * 68 + tx * 8 + j]        = s0[j];
            Ss[(ty + 64) * 68 + tx * 8 + j] = s1[j];
        }
        __syncthreads();

        float sv[16];
        float mloc = -1e30f;
#pragma unroll
        for (int i = 0; i < 16; i++) {
            sv[i] = Ss[rr * 68 + rq * 16 + i] + madd[rq * 16 + i];
            mloc = fmaxf(mloc, sv[i]);
        }
        mloc = fmaxf(mloc, __shfl_xor_sync(0xffffffffu, mloc, 1));
        mloc = fmaxf(mloc, __shfl_xor_sync(0xffffffffu, mloc, 2));
        float mold = mrow[rr];
        float mnew = fmaxf(mold, mloc);
        float psum = 0.f;
#pragma unroll
        for (int i = 0; i < 16; i++) {
            float e = __expf(sv[i] - mnew);
            Ss[rr * 68 + rq * 16 + i] = e;
            psum += e;
        }
        psum += __shfl_xor_sync(0xffffffffu, psum, 1);
        psum += __shfl_xor_sync(0xffffffffu, psum, 2);
        if (rq == 0) {
            float corr = __expf(mold - mnew);
            crow[rr] = corr;
            lrow[rr] = lrow[rr] * corr + psum;
            mrow[rr] = mnew;
        }
        __syncthreads();

        float c0 = crow[ty], c1 = crow[ty + 64];
#pragma unroll
        for (int i = 0; i < 16; i++) { o0[i] *= c0; o1[i] *= c1; }
#pragma unroll 2
        for (int j = 0; j < ABK; ++j) {
            float p0 = Ss[ty * 68 + j];
            float p1 = Ss[(ty + 64) * 68 + j];
            float vr[16];
            *(float4*)&vr[0]  = *(const float4*)&Vs[j * 132 + tx * 16];
            *(float4*)&vr[4]  = *(const float4*)&Vs[j * 132 + tx * 16 + 4];
            *(float4*)&vr[8]  = *(const float4*)&Vs[j * 132 + tx * 16 + 8];
            *(float4*)&vr[12] = *(const float4*)&Vs[j * 132 + tx * 16 + 12];
#pragma unroll
            for (int i = 0; i < 16; i++) { o0[i] += p0 * vr[i]; o1[i] += p1 * vr[i]; }
        }
    }
    __syncthreads();

    float inv0 = 1.0f / lrow[ty];
    float inv1 = 1.0f / lrow[ty + 64];
#pragma unroll
    for (int i = 0; i < 16; i += 4) {
        float4 a, c;
        a.x = o0[i] * inv0; a.y = o0[i + 1] * inv0;
        a.z = o0[i + 2] * inv0; a.w = o0[i + 3] * inv0;
        *(float4*)(g_ctx + base + (size_t)(q0 + ty) * D_MODEL + tx * 16 + i) = a;
        c.x = o1[i] * inv1; c.y = o1[i + 1] * inv1;
        c.z = o1[i + 2] * inv1; c.w = o1[i + 3] * inv1;
        *(float4*)(g_ctx + base + (size_t)(q0 + ty + 64) * D_MODEL + tx * 16 + i) = c;
    }
}

// ============================================================
extern "C" void kernel_launch(void* const* d_in, const int* in_sizes, int n_in,
                              void* d_out, int out_size)
{
    const float* x    = (const float*)d_in[0];
    const float* mask = (const float*)d_in[1];
    const float* Wq   = (const float*)d_in[2];
    const float* bq   = (const float*)d_in[3];
    const float* Wk   = (const float*)d_in[4];
    const float* bk   = (const float*)d_in[5];
    const float* Wv   = (const float*)d_in[6];
    const float* bv   = (const float*)d_in[7];
    const float* Wo   = (const float*)d_in[8];
    const float* bo   = (const float*)d_in[9];
    float* out = (float*)d_out;

    float *q, *k, *v, *ctx;
    cudaGetSymbolAddress((void**)&q,   g_q);
    cudaGetSymbolAddress((void**)&k,   g_k);
    cudaGetSymbolAddress((void**)&v,   g_v);
    cudaGetSymbolAddress((void**)&ctx, g_ctx);
    __nv_bfloat16 *xh, *xl, *ch, *cl, *wh, *wl;
    cudaGetSymbolAddress((void**)&xh, g_xh);
    cudaGetSymbolAddress((void**)&xl, g_xl);
    cudaGetSymbolAddress((void**)&ch, g_chh);
    cudaGetSymbolAddress((void**)&cl, g_cll);
    cudaGetSymbolAddress((void**)&wh, g_wh);
    cudaGetSymbolAddress((void**)&wl, g_wl);

    const int WN = D_MODEL * D_MODEL;
    const int XN = M_TOK * D_MODEL;
    const float scale = 0.08838834764831845f;  // 1/sqrt(128)

    // split + pack (tile-contiguous, pre-swizzled)
    split_pack<<<XN / 8 / 256, 256>>>(x, xh, xl, NRT_A, XN / 8);
    split_pack<<<WN / 8 / 256, 256>>>(Wq, wh + 0ll * WN, wl + 0ll * WN, NRT_W, WN / 8);
    split_pack<<<WN / 8 / 256, 256>>>(Wk, wh + 1ll * WN, wl + 1ll * WN, NRT_W, WN / 8);
    split_pack<<<WN / 8 / 256, 256>>>(Wv, wh + 2ll * WN, wl + 2ll * WN, NRT_W, WN / 8);
    split_pack<<<WN / 8 / 256, 256>>>(Wo, wh + 3ll * WN, wl + 3ll * WN, NRT_W, WN / 8);

    cudaFuncSetAttribute(gemm_tc, cudaFuncAttributeMaxDynamicSharedMemorySize, GEMM_SMEM);
    dim3 ggrid(D_MODEL / 256, M_TOK / 128);   // 8 x 32 = 256 CTAs
    gemm_tc<<<ggrid, 256, GEMM_SMEM>>>(xh, xl, wh + 0ll * WN, wl + 0ll * WN, bq, q, scale);
    gemm_tc<<<ggrid, 256, GEMM_SMEM>>>(xh, xl, wh + 1ll * WN, wl + 1ll * WN, bk, k, 1.0f);
    gemm_tc<<<ggrid, 256, GEMM_SMEM>>>(xh, xl, wh + 2ll * WN, wl + 2ll * WN, bv, v, 1.0f);

    cudaFuncSetAttribute(attn_kernel, cudaFuncAttributeMaxDynamicSharedMemorySize,
                         SMEM_FLOATS * 4);
    attn_kernel<<<dim3(SEQ / ABQ, BATCH * NHEADS), 512, SMEM_FLOATS * 4>>>(mask);

    split_pack<<<XN / 8 / 256, 256>>>(ctx, ch, cl, NRT_A, XN / 8);
    gemm_tc<<<ggrid, 256, GEMM_SMEM>>>(ch, cl, wh + 3ll * WN, wl + 3ll * WN, bo, out, 1.0f);
}

// round 5
// speedup vs baseline: 12.1173x; 8.6694x over previous
#include <cuda_runtime.h>
#include <cuda_bf16.h>
#include <cstdint>

#define D_MODEL 2048
#define SEQ     2048
#define BATCH   2
#define NHEADS  16
#define HDIM    128
#define M_TOK   (BATCH*SEQ)   // 4096

#if defined(__CUDA_ARCH_FEAT_SM103_ALL) || defined(__CUDA_ARCH_FEAT_SM100_ALL) || \
    (defined(__CUDA_ARCH_SPECIFIC__) && (__CUDA_ARCH_SPECIFIC__ >= 1000))
#define HAS_TCGEN05 1
#else
#define HAS_TCGEN05 0
#endif

// ---- persistent scratch ----
__device__ float g_q[M_TOK * D_MODEL];
__device__ float g_k[M_TOK * D_MODEL];
__device__ float g_v[M_TOK * D_MODEL];
__device__ float g_ctx[M_TOK * D_MODEL];

// packed GEMM operands (tile-contiguous, pre-swizzled)
__device__ __nv_bfloat16 g_xh[M_TOK * D_MODEL];
__device__ __nv_bfloat16 g_xl[M_TOK * D_MODEL];
__device__ __nv_bfloat16 g_chh[M_TOK * D_MODEL];
__device__ __nv_bfloat16 g_cll[M_TOK * D_MODEL];
__device__ __nv_bfloat16 g_wh[4][D_MODEL * D_MODEL];
__device__ __nv_bfloat16 g_wl[4][D_MODEL * D_MODEL];

// packed attention operands
__device__ __nv_bfloat16 g_aqh[M_TOK * D_MODEL];   // Q tiles: [bh][rt16][2ch x 16KB]
__device__ __nv_bfloat16 g_aql[M_TOK * D_MODEL];
__device__ __nv_bfloat16 g_akh[M_TOK * D_MODEL];   // K tiles: [bh][kt32][2ch x 8KB]
__device__ __nv_bfloat16 g_akl[M_TOK * D_MODEL];
__device__ __nv_bfloat16 g_avh[M_TOK * D_MODEL];   // V^T tiles: [bh][kt32][16KB]
__device__ __nv_bfloat16 g_avl[M_TOK * D_MODEL];

// ============================================================
// PTX helpers
// ============================================================
__device__ __forceinline__ uint32_t smem_u32(const void* p) {
    uint32_t a;
    asm("{ .reg .u64 t; cvta.to.shared.u64 t, %1; cvt.u32.u64 %0, t; }" : "=r"(a) : "l"(p));
    return a;
}
__device__ __forceinline__ uint32_t elect_one_pred() {
    uint32_t p;
    asm volatile("{ .reg .pred p; elect.sync _|p, 0xFFFFFFFF; selp.b32 %0, 1, 0, p; }" : "=r"(p));
    return p;
}
static constexpr uint64_t SMEM_DESC_BASE_SW128 =
    (uint64_t(2) << 61) | (uint64_t(1) << 46) | (uint64_t(64) << 32) | (uint64_t(1) << 16);
#define MAKE_SMEM_DESC(base_addr) \
    (SMEM_DESC_BASE_SW128 | ((uint64_t)((base_addr) >> 4) & 0x3FFF))
#define SMEM_SWIZZLE_128B(off) ((off) ^ (((off) >> 3) & 0x70))

#define MBARRIER_INIT(mbar, count) \
    asm volatile("mbarrier.init.shared.b64 [%0], %1;" \
                 :: "r"((uint32_t)(mbar)), "r"((uint32_t)(count)) : "memory")
#define MBARRIER_INVAL(mbar) \
    asm volatile("mbarrier.inval.shared.b64 [%0];" :: "r"((uint32_t)(mbar)) : "memory")
#define MBARRIER_EXPECT_TX(mbar, bytes) \
    asm volatile("mbarrier.arrive.expect_tx.shared.b64 _, [%0], %1;" \
                 :: "r"((uint32_t)(mbar)), "r"((uint32_t)(bytes)) : "memory")
#define MBARRIER_ARRIVE(mbar) \
    asm volatile("mbarrier.arrive.shared.b64 _, [%0];" :: "r"((uint32_t)(mbar)) : "memory")
#define MBARRIER_WAIT_PARITY(mbar, parity) do {                                          \
    uint32_t _m = (uint32_t)(mbar);                                                      \
    uint32_t _p = (uint32_t)(parity);                                                    \
    uint32_t _done;                                                                      \
    asm volatile("{ .reg .pred p; mbarrier.try_wait.parity.acquire.cta.shared::cta.b64 " \
                 "p, [%1], %2; selp.b32 %0, 1, 0, p; }"                                  \
                 : "=r"(_done) : "r"(_m), "r"(_p) : "memory");                           \
    if (!_done) {                                                                        \
        asm volatile("{ .reg .pred P1; WL_%=: "                                          \
                     "mbarrier.try_wait.parity.acquire.cta.shared::cta.b64 P1, [%0], %1, 0x989680; " \
                     "@P1 bra.uni WD_%=; bra.uni WL_%=; WD_%=: }"                        \
                     :: "r"(_m), "r"(_p) : "memory");                                    \
    }                                                                                    \
} while (0)

#define BULK_CP(dst_smem, src_gmem, bytes, mbar) \
    asm volatile("cp.async.bulk.shared::cluster.global.mbarrier::complete_tx::bytes " \
                 "[%0], [%1], %2, [%3];" \
                 :: "r"((uint32_t)(dst_smem)), "l"(src_gmem), "r"((uint32_t)(bytes)), \
                    "r"((uint32_t)(mbar)) : "memory")

#if HAS_TCGEN05
#define TCGEN05_ALLOC(smem_addr, nCols) \
    asm volatile("tcgen05.alloc.cta_group::1.sync.aligned.shared::cta.b32 [%0], %1;" \
                 :: "r"((uint32_t)(smem_addr)), "r"((uint32_t)(nCols)) : "memory")
#define TCGEN05_DEALLOC(tmem_addr, nCols) \
    asm volatile("tcgen05.dealloc.cta_group::1.sync.aligned.b32 %0, %1;" \
                 :: "r"(tmem_addr), "r"((uint32_t)(nCols)))
#define TCGEN05_RELINQUISH() \
    asm volatile("tcgen05.relinquish_alloc_permit.cta_group::1.sync.aligned;")
#define TCGEN05_COMMIT(mbar) \
    asm volatile("tcgen05.commit.cta_group::1.mbarrier::arrive::one.shared::cluster.b64 [%0];" \
                 :: "r"((uint32_t)(mbar)) : "memory")
#define TCGEN05_FENCE_AFTER() \
    asm volatile("tcgen05.fence::after_thread_sync;" ::: "memory")
#define TCGEN05_FENCE_BEFORE() \
    asm volatile("tcgen05.fence::before_thread_sync;" ::: "memory")
#define TCGEN05_WAIT_LD() \
    asm volatile("tcgen05.wait::ld.sync.aligned;" ::: "memory")
#define TCGEN05_WAIT_ST() \
    asm volatile("tcgen05.wait::st.sync.aligned;" ::: "memory")

#define TCGEN05_LD_32X32B_X32(r, tmem_addr) \
    asm volatile( \
        "tcgen05.ld.sync.aligned.32x32b.x32.b32 " \
        "{%0, %1, %2, %3, %4, %5, %6, %7, " \
        " %8, %9, %10, %11, %12, %13, %14, %15, " \
        " %16, %17, %18, %19, %20, %21, %22, %23, " \
        " %24, %25, %26, %27, %28, %29, %30, %31}, [%32];" \
        : "=r"((r)[0]),  "=r"((r)[1]),  "=r"((r)[2]),  "=r"((r)[3]), \
          "=r"((r)[4]),  "=r"((r)[5]),  "=r"((r)[6]),  "=r"((r)[7]), \
          "=r"((r)[8]),  "=r"((r)[9]),  "=r"((r)[10]), "=r"((r)[11]), \
          "=r"((r)[12]), "=r"((r)[13]), "=r"((r)[14]), "=r"((r)[15]), \
          "=r"((r)[16]), "=r"((r)[17]), "=r"((r)[18]), "=r"((r)[19]), \
          "=r"((r)[20]), "=r"((r)[21]), "=r"((r)[22]), "=r"((r)[23]), \
          "=r"((r)[24]), "=r"((r)[25]), "=r"((r)[26]), "=r"((r)[27]), \
          "=r"((r)[28]), "=r"((r)[29]), "=r"((r)[30]), "=r"((r)[31]) \
        : "r"(tmem_addr))

#define TCGEN05_ST_32X32B_X32(tmem_addr, r) \
    asm volatile( \
        "tcgen05.st.sync.aligned.32x32b.x32.b32 [%0], " \
        "{%1, %2, %3, %4, %5, %6, %7, %8, " \
        " %9, %10, %11, %12, %13, %14, %15, %16, " \
        " %17, %18, %19, %20, %21, %22, %23, %24, " \
        " %25, %26, %27, %28, %29, %30, %31, %32};" \
        :: "r"(tmem_addr), \
           "r"((r)[0]),  "r"((r)[1]),  "r"((r)[2]),  "r"((r)[3]), \
           "r"((r)[4]),  "r"((r)[5]),  "r"((r)[6]),  "r"((r)[7]), \
           "r"((r)[8]),  "r"((r)[9]),  "r"((r)[10]), "r"((r)[11]), \
           "r"((r)[12]), "r"((r)[13]), "r"((r)[14]), "r"((r)[15]), \
           "r"((r)[16]), "r"((r)[17]), "r"((r)[18]), "r"((r)[19]), \
           "r"((r)[20]), "r"((r)[21]), "r"((r)[22]), "r"((r)[23]), \
           "r"((r)[24]), "r"((r)[25]), "r"((r)[26]), "r"((r)[27]), \
           "r"((r)[28]), "r"((r)[29]), "r"((r)[30]), "r"((r)[31]) \
        : "memory")

__device__ __forceinline__ void mma_f16_ss(uint32_t d_tmem, uint64_t a_desc, uint64_t b_desc,
                                           uint32_t idesc, uint32_t enable) {
    asm volatile(
        "{\n\t"
        ".reg .pred p;\n\t"
        "setp.ne.u32 p, %4, 0;\n\t"
        "tcgen05.mma.cta_group::1.kind::f16 [%0], %1, %2, %3, {%5, %5, %5, %5}, p;\n\t"
        "}"
        :: "r"(d_tmem), "l"(a_desc), "l"(b_desc), "r"(idesc), "r"(enable), "r"(0u)
        : "memory");
}
__device__ __forceinline__ void mma_f16_ts(uint32_t d_tmem, uint32_t a_tmem, uint64_t b_desc,
                                           uint32_t idesc, uint32_t enable) {
    asm volatile(
        "{\n\t"
        ".reg .pred p;\n\t"
        "setp.ne.u32 p, %4, 0;\n\t"
        "tcgen05.mma.cta_group::1.kind::f16 [%0], [%1], %2, %3, {%5, %5, %5, %5}, p;\n\t"
        "}"
        :: "r"(d_tmem), "r"(a_tmem), "l"(b_desc), "r"(idesc), "r"(enable), "r"(0u)
        : "memory");
}
#endif  // HAS_TCGEN05

// ============================================================
// GEMM operand split+pack (unchanged from R4)
// ============================================================
__global__ __launch_bounds__(256) void split_pack(
    const float* __restrict__ src, __nv_bfloat16* __restrict__ hi,
    __nv_bfloat16* __restrict__ lo, int nrt, int n8)
{
    int i = blockIdx.x * blockDim.x + threadIdx.x;
    if (i >= n8) return;
    int elem = i * 8;
    int row = elem >> 11;
    int col = elem & 2047;
    int rt = row >> 7, r = row & 127;
    int c  = col >> 6, kc = col & 63;
    size_t tb = ((size_t)(c * nrt + rt)) << 14;
    uint32_t so = SMEM_SWIZZLE_128B((uint32_t)(r * 128 + kc * 2));

    float4 v0 = ((const float4*)src)[i * 2];
    float4 v1 = ((const float4*)src)[i * 2 + 1];
    float f[8] = {v0.x, v0.y, v0.z, v0.w, v1.x, v1.y, v1.z, v1.w};
    __nv_bfloat16 h[8], l[8];
#pragma unroll
    for (int j = 0; j < 8; j++) {
        h[j] = __float2bfloat16(f[j]);
        l[j] = __float2bfloat16(f[j] - __bfloat162float(h[j]));
    }
    *(uint4*)((char*)hi + tb + so) = *(uint4*)h;
    *(uint4*)((char*)lo + tb + so) = *(uint4*)l;
}

// ============================================================
// Attention operand packers: fp32 [tok,2048] -> bf16 hi/lo swizzled tiles
// ============================================================
__global__ __launch_bounds__(256) void pack_q_attn(int n8)
{
    int i = blockIdx.x * blockDim.x + threadIdx.x;
    if (i >= n8) return;
    int elem = i * 8;
    int tok = elem >> 11, col = elem & 2047;
    int b = tok >> 11, s = tok & 2047;
    int h = col >> 7, d = col & 127;
    int bh = b * 16 + h, rt = s >> 7, r = s & 127, ch = d >> 6, kc = d & 63;
    size_t tb = ((size_t)(((bh * 16 + rt) * 2) + ch)) << 14;
    uint32_t so = SMEM_SWIZZLE_128B((uint32_t)(r * 128 + kc * 2));
    const float* src = g_q + (size_t)tok * 2048 + col;
    float4 v0 = *(const float4*)src, v1 = *(const float4*)(src + 4);
    float f[8] = {v0.x, v0.y, v0.z, v0.w, v1.x, v1.y, v1.z, v1.w};
    __nv_bfloat16 hh[8], ll[8];
#pragma unroll
    for (int j = 0; j < 8; j++) {
        hh[j] = __float2bfloat16(f[j]);
        ll[j] = __float2bfloat16(f[j] - __bfloat162float(hh[j]));
    }
    *(uint4*)((char*)g_aqh + tb + so) = *(uint4*)hh;
    *(uint4*)((char*)g_aql + tb + so) = *(uint4*)ll;
}

__global__ __launch_bounds__(256) void pack_k_attn(int n8)
{
    int i = blockIdx.x * blockDim.x + threadIdx.x;
    if (i >= n8) return;
    int elem = i * 8;
    int tok = elem >> 11, col = elem & 2047;
    int b = tok >> 11, s = tok & 2047;
    int h = col >> 7, d = col & 127;
    int bh = b * 16 + h, kt = s >> 6, r = s & 63, ch = d >> 6, kc = d & 63;
    size_t tb = ((size_t)(((bh * 32 + kt) * 2) + ch)) << 13;
    uint32_t so = SMEM_SWIZZLE_128B((uint32_t)(r * 128 + kc * 2));
    const float* src = g_k + (size_t)tok * 2048 + col;
    float4 v0 = *(const float4*)src, v1 = *(const float4*)(src + 4);
    float f[8] = {v0.x, v0.y, v0.z, v0.w, v1.x, v1.y, v1.z, v1.w};
    __nv_bfloat16 hh[8], ll[8];
#pragma unroll
    for (int j = 0; j < 8; j++) {
        hh[j] = __float2bfloat16(f[j]);
        ll[j] = __float2bfloat16(f[j] - __bfloat162float(hh[j]));
    }
    *(uint4*)((char*)g_akh + tb + so) = *(uint4*)hh;
    *(uint4*)((char*)g_akl + tb + so) = *(uint4*)ll;
}

__global__ __launch_bounds__(256) void pack_vt_attn(int n8)
{
    int i = blockIdx.x * blockDim.x + threadIdx.x;
    if (i >= n8) return;
    int elem = i * 8;
    int tok = elem >> 11, col = elem & 2047;
    int b = tok >> 11, s = tok & 2047;
    int h = col >> 7, d = col & 127;
    int bh = b * 16 + h, kt = s >> 6, sc = s & 63;
    size_t tb = ((size_t)(bh * 32 + kt)) << 14;
    const float* src = g_v + (size_t)tok * 2048 + col;
    float4 v0 = *(const float4*)src, v1 = *(const float4*)(src + 4);
    float f[8] = {v0.x, v0.y, v0.z, v0.w, v1.x, v1.y, v1.z, v1.w};
#pragma unroll
    for (int j = 0; j < 8; j++) {
        __nv_bfloat16 hh = __float2bfloat16(f[j]);
        __nv_bfloat16 ll = __float2bfloat16(f[j] - __bfloat162float(hh));
        uint32_t off = SMEM_SWIZZLE_128B((uint32_t)((d + j) * 128 + sc * 2));
        *(__nv_bfloat16*)((char*)g_avh + tb + off) = hh;
        *(__nv_bfloat16*)((char*)g_avl + tb + off) = ll;
    }
}

// ============================================================
// tcgen05 GEMM (unchanged from R4)
// ============================================================
#define KCH  64
#define NCH  (D_MODEL / KCH)
#define NRT_A 32
#define NRT_W 16
#define TIL  16384
#define STG  (6 * TIL)
#define SMB0 1024
#define GEMM_SMEM (SMB0 + 2 * STG)
#define GEMM_IDESC 0x8400490u

__global__ __launch_bounds__(256) void gemm_tc(
    const __nv_bfloat16* __restrict__ Ah, const __nv_bfloat16* __restrict__ Al,
    const __nv_bfloat16* __restrict__ Bh, const __nv_bfloat16* __restrict__ Bl,
    const float* __restrict__ bias, float* __restrict__ C, float alpha)
{
#if HAS_TCGEN05
    extern __shared__ char sm[];
    const uint32_t smb = smem_u32(sm);
    const int tid = threadIdx.x;
    const int wid = tid >> 5;
    const int lid = tid & 31;
    const int rm = blockIdx.y;
    const int bx = blockIdx.x;

    if (wid == 0) TCGEN05_ALLOC(smb + 0, 256);
    if (tid == 0) {
#pragma unroll
        for (int s = 0; s < 2; ++s) {
            MBARRIER_INIT(smb + 64 + 16 * s, 1);
            MBARRIER_INIT(smb + 96 + 16 * s, 1);
        }
    }
    __syncthreads();

    uint32_t tmem;
    asm volatile("ld.shared.b32 %0, [%1];" : "=r"(tmem) : "r"(smb + 0));

    if (wid == 0 && elect_one_pred()) {
        const char* pAh = (const char*)Ah;
        const char* pAl = (const char*)Al;
        const char* pBh = (const char*)Bh;
        const char* pBl = (const char*)Bl;

#define LOAD_CHUNK(c, s)                                                        \
        do {                                                                    \
            uint32_t st = smb + SMB0 + (s) * STG;                               \
            uint32_t fb = smb + 64 + 16 * (s);                                  \
            size_t ao = ((size_t)((c) * NRT_A + rm)) << 14;                     \
            size_t bo = ((size_t)((c) * NRT_W + 2 * bx)) << 14;                 \
            MBARRIER_EXPECT_TX(fb, 6 * TIL);                                    \
            BULK_CP(st,           pAh + ao, TIL,     fb);                       \
            BULK_CP(st + TIL,     pAl + ao, TIL,     fb);                       \
            BULK_CP(st + 2 * TIL, pBh + bo, 2 * TIL, fb);                       \
            BULK_CP(st + 4 * TIL, pBl + bo, 2 * TIL, fb);                       \
        } while (0)

        LOAD_CHUNK(0, 0);
        LOAD_CHUNK(1, 1);

        for (int c = 0; c < NCH; ++c) {
            int s = c & 1, ph = (c >> 1) & 1;
            uint32_t st = smb + SMB0 + s * STG;
            MBARRIER_WAIT_PARITY(smb + 64 + 16 * s, ph);
            uint64_t dAh = MAKE_SMEM_DESC(st);
            uint64_t dAl = MAKE_SMEM_DESC(st + TIL);
            uint64_t dBh = MAKE_SMEM_DESC(st + 2 * TIL);
            uint64_t dBl = MAKE_SMEM_DESC(st + 4 * TIL);
#pragma unroll
            for (int ks = 0; ks < 4; ++ks) {
                mma_f16_ss(tmem, dAh + ks * 2, dBh + ks * 2, GEMM_IDESC, (c | ks) != 0);
                mma_f16_ss(tmem, dAl + ks * 2, dBh + ks * 2, GEMM_IDESC, 1);
                mma_f16_ss(tmem, dAh + ks * 2, dBl + ks * 2, GEMM_IDESC, 1);
            }
            TCGEN05_COMMIT(smb + 96 + 16 * s);
            if (c + 2 < NCH) {
                MBARRIER_WAIT_PARITY(smb + 96 + 16 * s, ph);
                LOAD_CHUNK(c + 2, s);
            }
        }
        MBARRIER_WAIT_PARITY(smb + 96 + 16 * ((NCH - 1) & 1), ((NCH - 1) >> 1) & 1);
#undef LOAD_CHUNK
    }
    __syncthreads();
    TCGEN05_FENCE_AFTER();

    const int wg = wid >> 2;
    const int sub = wid & 3;
    const int m = blockIdx.y * 128 + sub * 32 + lid;
    float* crow = C + (size_t)m * D_MODEL;
#pragma unroll
    for (int cb = 0; cb < 4; ++cb) {
        uint32_t r[32];
        TCGEN05_LD_32X32B_X32(r, tmem + wg * 128 + cb * 32);
        TCGEN05_WAIT_LD();
        int n0 = bx * 256 + wg * 128 + cb * 32;
#pragma unroll
        for (int j = 0; j < 32; j += 4) {
            float4 o;
            o.x = (__uint_as_float(r[j + 0]) + bias[n0 + j + 0]) * alpha;
            o.y = (__uint_as_float(r[j + 1]) + bias[n0 + j + 1]) * alpha;
            o.z = (__uint_as_float(r[j + 2]) + bias[n0 + j + 2]) * alpha;
            o.w = (__uint_as_float(r[j + 3]) + bias[n0 + j + 3]) * alpha;
            *(float4*)(crow + n0 + j) = o;
        }
    }
    TCGEN05_FENCE_BEFORE();

    __syncthreads();
    if (tid == 0) {
#pragma unroll
        for (int s = 0; s < 2; ++s) {
            MBARRIER_INVAL(smb + 64 + 16 * s);
            MBARRIER_INVAL(smb + 96 + 16 * s);
        }
    }
    __syncthreads();
    if (wid == 0) {
        TCGEN05_RELINQUISH();
        TCGEN05_DEALLOC(tmem, 256);
    }
#endif
}

// ============================================================
// tcgen05 flash attention, no-max softmax, O accum in TMEM
// grid (16 q-tiles, 32 bh), 160 threads: warps 0-3 softmax, warp 4 control
// ============================================================
#define AOFF_Q    1024
#define AOFF_MADD 66560            // 1024 + 65536
#define AOFF_ST   74752            // + 8192
#define ASTG      65536            // Kh 16K | Kl 16K | VTh 16K | VTl 16K
#define ATTN_SMEM 205824           // 74752 + 2*65536
// mbarriers: full_kv@64+16s, s_full@96+16s, smax_free@128+16s,
//            p_ready@160+16s, pv_done@192+16s
#define IDESC_S   0x8100490u       // M=128, N=64
#define IDESC_PV  0x8200490u       // M=128, N=128
// TMEM cols: S0=0, S1=64, O=128, P0h=256, P0l=288, P1h=320, P1l=352

__global__ __launch_bounds__(160) void attn_tc(const float* __restrict__ mask)
{
#if HAS_TCGEN05
    extern __shared__ char sm[];
    const uint32_t smb = smem_u32(sm);
    const int tid = threadIdx.x;
    const int wid = tid >> 5;
    const int lid = tid & 31;
    const int rt = blockIdx.x;       // q tile 0..15
    const int bh = blockIdx.y;       // 0..31
    const int b = bh >> 4;

    if (wid == 0) TCGEN05_ALLOC(smb + 0, 512);
    if (tid == 0) {
#pragma unroll
        for (int s = 0; s < 2; ++s) {
            MBARRIER_INIT(smb + 64 + 16 * s, 1);    // full_kv
            MBARRIER_INIT(smb + 96 + 16 * s, 1);    // s_full (commit)
            MBARRIER_INIT(smb + 128 + 16 * s, 4);   // smax_free
            MBARRIER_INIT(smb + 160 + 16 * s, 4);   // p_ready
            MBARRIER_INIT(smb + 192 + 16 * s, 1);   // pv_done (commit)
        }
    }
    // mask -> additive bias in smem
    for (int j = tid; j < SEQ; j += 160) {
        float mv = mask[b * SEQ + j];
        ((float*)(sm + AOFF_MADD))[j] = (1.0f - mv) * -1e30f;
    }
    __syncthreads();

    uint32_t tmem;
    asm volatile("ld.shared.b32 %0, [%1];" : "=r"(tmem) : "r"(smb + 0));

    if (wid == 4) {
        if (elect_one_pred()) {
            const char* akh = (const char*)g_akh;
            const char* akl = (const char*)g_akl;
            const char* avh = (const char*)g_avh;
            const char* avl = (const char*)g_avl;

#define LOADKV(i2, s2, mb)                                              \
            do {                                                        \
                size_t kb = ((size_t)(bh * 32 + (i2))) << 14;           \
                uint32_t st_ = smb + AOFF_ST + (s2) * ASTG;             \
                BULK_CP(st_,         akh + kb, 16384, mb);              \
                BULK_CP(st_ + 16384, akl + kb, 16384, mb);              \
                BULK_CP(st_ + 32768, avh + kb, 16384, mb);              \
                BULK_CP(st_ + 49152, avl + kb, 16384, mb);              \
            } while (0)

            // prologue: Q + stage0 on full_kv[0]; stage1 on full_kv[1]
            {
                size_t qb = ((size_t)(bh * 16 + rt)) << 15;
                MBARRIER_EXPECT_TX(smb + 64, 131072);
                BULK_CP(smb + AOFF_Q,         (const char*)g_aqh + qb, 32768, smb + 64);
                BULK_CP(smb + AOFF_Q + 32768, (const char*)g_aql + qb, 32768, smb + 64);
                LOADKV(0, 0, smb + 64);
                MBARRIER_EXPECT_TX(smb + 80, 65536);
                LOADKV(1, 1, smb + 80);
            }
            const uint64_t dQh = MAKE_SMEM_DESC(smb + AOFF_Q);
            const uint64_t dQl = MAKE_SMEM_DESC(smb + AOFF_Q + 32768);

            for (int i = 0; i < 32; ++i) {
                int s = i & 1, ph = (i >> 1) & 1;
                MBARRIER_WAIT_PARITY(smb + 64 + 16 * s, ph);
                if (i >= 2) MBARRIER_WAIT_PARITY(smb + 128 + 16 * s, ((i - 2) >> 1) & 1);
                uint32_t sreg = tmem + s * 64;
                uint32_t stg = smb + AOFF_ST + s * ASTG;
                uint64_t dKh = MAKE_SMEM_DESC(stg);
                uint64_t dKl = MAKE_SMEM_DESC(stg + 16384);
#pragma unroll
                for (int ch = 0; ch < 2; ++ch)
#pragma unroll
                for (int ks = 0; ks < 4; ++ks) {
                    uint64_t ao = ch * 1024 + ks * 2;
                    uint64_t bo = ch * 512 + ks * 2;
                    mma_f16_ss(sreg, dQh + ao, dKh + bo, IDESC_S, (ch | ks) != 0);
                    mma_f16_ss(sreg, dQl + ao, dKh + bo, IDESC_S, 1);
                    mma_f16_ss(sreg, dQh + ao, dKl + bo, IDESC_S, 1);
                }
                TCGEN05_COMMIT(smb + 96 + 16 * s);

                if (i >= 1) {
                    int j = i - 1, sj = j & 1, pj = (j >> 1) & 1;
                    MBARRIER_WAIT_PARITY(smb + 160 + 16 * sj, pj);
                    TCGEN05_FENCE_AFTER();
                    uint32_t stj = smb + AOFF_ST + sj * ASTG;
                    uint64_t dVh = MAKE_SMEM_DESC(stj + 32768);
                    uint64_t dVl = MAKE_SMEM_DESC(stj + 49152);
#pragma unroll
                    for (int ks = 0; ks < 4; ++ks) {
                        uint32_t ah = tmem + 256 + sj * 64 + ks * 8;
                        uint32_t al = tmem + 288 + sj * 64 + ks * 8;
                        uint64_t bo = (uint64_t)(ks * 2);
                        mma_f16_ts(tmem + 128, ah, dVh + bo, IDESC_PV, (j | ks) != 0);
                        mma_f16_ts(tmem + 128, al, dVh + bo, IDESC_PV, 1);
                        mma_f16_ts(tmem + 128, ah, dVl + bo, IDESC_PV, 1);
                    }
                    TCGEN05_COMMIT(smb + 192 + 16 * sj);
                    MBARRIER_WAIT_PARITY(smb + 192 + 16 * sj, pj);
                    if (i < 31) {
                        uint32_t fb = smb + 64 + 16 * ((i + 1) & 1);
                        MBARRIER_EXPECT_TX(fb, 65536);
                        LOADKV(i + 1, (i + 1) & 1, fb);
                    }
                }
            }
            // final PV: j = 31
            {
                int sj = 1, pj = 1;
                MBARRIER_WAIT_PARITY(smb + 160 + 16 * sj, pj);
                TCGEN05_FENCE_AFTER();
                uint32_t stj = smb + AOFF_ST + sj * ASTG;
                uint64_t dVh = MAKE_SMEM_DESC(stj + 32768);
                uint64_t dVl = MAKE_SMEM_DESC(stj + 49152);
#pragma unroll
                for (int ks = 0; ks < 4; ++ks) {
                    uint32_t ah = tmem + 256 + sj * 64 + ks * 8;
                    uint32_t al = tmem + 288 + sj * 64 + ks * 8;
                    uint64_t bo = (uint64_t)(ks * 2);
                    mma_f16_ts(tmem + 128, ah, dVh + bo, IDESC_PV, 1);
                    mma_f16_ts(tmem + 128, al, dVh + bo, IDESC_PV, 1);
                    mma_f16_ts(tmem + 128, ah, dVl + bo, IDESC_PV, 1);
                }
                TCGEN05_COMMIT(smb + 192 + 16 * sj);
                MBARRIER_WAIT_PARITY(smb + 192 + 16 * sj, pj);
            }
#undef LOADKV
        }
    }

    float l = 0.0f;
    if (wid < 4) {
        const float* md_base = (const float*)(sm + AOFF_MADD);
        for (int i = 0; i < 32; ++i) {
            int s = i & 1, ph = (i >> 1) & 1;
            MBARRIER_WAIT_PARITY(smb + 96 + 16 * s, ph);
            TCGEN05_FENCE_AFTER();
            uint32_t r0[32], r1[32];
            TCGEN05_LD_32X32B_X32(r0, tmem + s * 64);
            TCGEN05_LD_32X32B_X32(r1, tmem + s * 64 + 32);
            TCGEN05_WAIT_LD();
            if (elect_one_pred()) MBARRIER_ARRIVE(smb + 128 + 16 * s);

            const float* md = md_base + i * 64;
#pragma unroll
            for (int j = 0; j < 32; ++j) {
                float e = __expf(__uint_as_float(r0[j]) + md[j]);
                l += e;
                r0[j] = __float_as_uint(e);
            }
#pragma unroll
            for (int j = 0; j < 32; ++j) {
                float e = __expf(__uint_as_float(r1[j]) + md[32 + j]);
                l += e;
                r1[j] = __float_as_uint(e);
            }
            uint32_t phv[32], plv[32];
#pragma unroll
            for (int p = 0; p < 16; ++p) {
                float e0 = __uint_as_float(r0[2 * p]), e1 = __uint_as_float(r0[2 * p + 1]);
                __nv_bfloat16 h0 = __float2bfloat16(e0), h1 = __float2bfloat16(e1);
                __nv_bfloat16 l0 = __float2bfloat16(e0 - __bfloat162float(h0));
                __nv_bfloat16 l1 = __float2bfloat16(e1 - __bfloat162float(h1));
                __nv_bfloat162 hp(h0, h1), lp(l0, l1);
                phv[p] = *(uint32_t*)&hp;
                plv[p] = *(uint32_t*)&lp;
            }
#pragma unroll
            for (int p = 0; p < 16; ++p) {
                float e0 = __uint_as_float(r1[2 * p]), e1 = __uint_as_float(r1[2 * p + 1]);
                __nv_bfloat16 h0 = __float2bfloat16(e0), h1 = __float2bfloat16(e1);
                __nv_bfloat16 l0 = __float2bfloat16(e0 - __bfloat162float(h0));
                __nv_bfloat16 l1 = __float2bfloat16(e1 - __bfloat162float(h1));
                __nv_bfloat162 hp(h0, h1), lp(l0, l1);
                phv[16 + p] = *(uint32_t*)&hp;
                plv[16 + p] = *(uint32_t*)&lp;
            }
            uint32_t wo = (uint32_t)wid << 21;
            TCGEN05_ST_32X32B_X32(tmem + 256 + s * 64 + wo, phv);
            TCGEN05_ST_32X32B_X32(tmem + 288 + s * 64 + wo, plv);
            TCGEN05_WAIT_ST();
            TCGEN05_FENCE_BEFORE();
            if (elect_one_pred()) MBARRIER_ARRIVE(smb + 160 + 16 * s);
        }
    }

    __syncthreads();

    if (wid < 4) {
        TCGEN05_FENCE_AFTER();
        float inv = 1.0f / l;
        int qrow = rt * 128 + wid * 32 + lid;
        float* dst = g_ctx + ((size_t)(b * SEQ + qrow)) * D_MODEL + (bh & 15) * HDIM;
#pragma unroll
        for (int cb = 0; cb < 4; ++cb) {
            uint32_t r[32];
            TCGEN05_LD_32X32B_X32(r, tmem + 128 + cb * 32);
            TCGEN05_WAIT_LD();
#pragma unroll
            for (int j = 0; j < 32; j += 4) {
                float4 o;
                o.x = __uint_as_float(r[j + 0]) * inv;
                o.y = __uint_as_float(r[j + 1]) * inv;
                o.z = __uint_as_float(r[j + 2]) * inv;
                o.w = __uint_as_float(r[j + 3]) * inv;
                *(float4*)(dst + cb * 32 + j) = o;
            }
        }
        TCGEN05_FENCE_BEFORE();
    }

    __syncthreads();
    if (tid == 0) {
#pragma unroll
        for (int s = 0; s < 2; ++s) {
            MBARRIER_INVAL(smb + 64 + 16 * s);
            MBARRIER_INVAL(smb + 96 + 16 * s);
            MBARRIER_INVAL(smb + 128 + 16 * s);
            MBARRIER_INVAL(smb + 160 + 16 * s);
            MBARRIER_INVAL(smb + 192 + 16 * s);
        }
    }
    __syncthreads();
    if (wid == 0) {
        TCGEN05_RELINQUISH();
        TCGEN05_DEALLOC(tmem, 512);
    }
#endif  // HAS_TCGEN05
}

// ============================================================
extern "C" void kernel_launch(void* const* d_in, const int* in_sizes, int n_in,
                              void* d_out, int out_size)
{
    const float* x    = (const float*)d_in[0];
    const float* mask = (const float*)d_in[1];
    const float* Wq   = (const float*)d_in[2];
    const float* bq   = (const float*)d_in[3];
    const float* Wk   = (const float*)d_in[4];
    const float* bk   = (const float*)d_in[5];
    const float* Wv   = (const float*)d_in[6];
    const float* bv   = (const float*)d_in[7];
    const float* Wo   = (const float*)d_in[8];
    const float* bo   = (const float*)d_in[9];
    float* out = (float*)d_out;

    float *q, *k, *v, *ctx;
    cudaGetSymbolAddress((void**)&q,   g_q);
    cudaGetSymbolAddress((void**)&k,   g_k);
    cudaGetSymbolAddress((void**)&v,   g_v);
    cudaGetSymbolAddress((void**)&ctx, g_ctx);
    __nv_bfloat16 *xh, *xl, *ch, *cl, *wh, *wl;
    cudaGetSymbolAddress((void**)&xh, g_xh);
    cudaGetSymbolAddress((void**)&xl, g_xl);
    cudaGetSymbolAddress((void**)&ch, g_chh);
    cudaGetSymbolAddress((void**)&cl, g_cll);
    cudaGetSymbolAddress((void**)&wh, g_wh);
    cudaGetSymbolAddress((void**)&wl, g_wl);

    const int WN = D_MODEL * D_MODEL;
    const int XN = M_TOK * D_MODEL;
    const float scale = 0.08838834764831845f;  // 1/sqrt(128)

    split_pack<<<XN / 8 / 256, 256>>>(x, xh, xl, NRT_A, XN / 8);
    split_pack<<<WN / 8 / 256, 256>>>(Wq, wh + 0ll * WN, wl + 0ll * WN, NRT_W, WN / 8);
    split_pack<<<WN / 8 / 256, 256>>>(Wk, wh + 1ll * WN, wl + 1ll * WN, NRT_W, WN / 8);
    split_pack<<<WN / 8 / 256, 256>>>(Wv, wh + 2ll * WN, wl + 2ll * WN, NRT_W, WN / 8);
    split_pack<<<WN / 8 / 256, 256>>>(Wo, wh + 3ll * WN, wl + 3ll * WN, NRT_W, WN / 8);

    cudaFuncSetAttribute(gemm_tc, cudaFuncAttributeMaxDynamicSharedMemorySize, GEMM_SMEM);
    dim3 ggrid(D_MODEL / 256, M_TOK / 128);
    gemm_tc<<<ggrid, 256, GEMM_SMEM>>>(xh, xl, wh + 0ll * WN, wl + 0ll * WN, bq, q, scale);
    gemm_tc<<<ggrid, 256, GEMM_SMEM>>>(xh, xl, wh + 1ll * WN, wl + 1ll * WN, bk, k, 1.0f);
    gemm_tc<<<ggrid, 256, GEMM_SMEM>>>(xh, xl, wh + 2ll * WN, wl + 2ll * WN, bv, v, 1.0f);

    pack_q_attn<<<XN / 8 / 256, 256>>>(XN / 8);
    pack_k_attn<<<XN / 8 / 256, 256>>>(XN / 8);
    pack_vt_attn<<<XN / 8 / 256, 256>>>(XN / 8);

    cudaFuncSetAttribute(attn_tc, cudaFuncAttributeMaxDynamicSharedMemorySize, ATTN_SMEM);
    attn_tc<<<dim3(16, 32), 160, ATTN_SMEM>>>(mask);

    split_pack<<<XN / 8 / 256, 256>>>(ctx, ch, cl, NRT_A, XN / 8);
    gemm_tc<<<ggrid, 256, GEMM_SMEM>>>(ch, cl, wh + 3ll * WN, wl + 3ll * WN, bo, out, 1.0f);
}